// round 11
// baseline (speedup 1.0000x reference)
#include <cuda_runtime.h>
#include <cuda_bf16.h>
#include <cuda_fp16.h>

typedef unsigned int u32;
typedef unsigned long long u64;
typedef unsigned short u16;

#define TT 1024

// ---- device scratch --------------------------------------------------------
__device__ __align__(1024) float g_xp0[(size_t)512 * 128 * 4096];
__device__ __align__(1024) float g_xp1[(size_t)512 * 128 * 4096];
__device__ __align__(1024) __half g_xf[(size_t)128 * 1024 * 1024];   // x fp16 A-image
__device__ __align__(1024) __half g_wif[(size_t)4096 * 1024];        // Wi fp16 B-image
__device__ __align__(1024) __nv_bfloat16 g_whh[(size_t)4096 * 1024]; // Wh bf16 hi
__device__ __align__(1024) __nv_bfloat16 g_whl[(size_t)4096 * 1024]; // Wh bf16 lo
// h images ping-pong: 16 chunks x [128 b x 64 k], 128B rows, unit u -> u^(b&7)
__device__ __align__(1024) __nv_bfloat16 g_hh[2][16 * 128 * 64];
__device__ __align__(1024) __nv_bfloat16 g_hl[2][16 * 128 * 64];
__device__ unsigned g_flags[128];   // per-CTA step-completion flags

// ---- PTX helpers (base sm_103 safe) ---------------------------------------
__device__ __forceinline__ u32 sptr(const void* p) {
    u32 a;
    asm("{ .reg .u64 t; cvta.to.shared.u64 t, %1; cvt.u32.u64 %0, t; }" : "=r"(a) : "l"(p));
    return a;
}
__device__ __forceinline__ void mbar_init(u32 m, u32 cnt) {
    asm volatile("mbarrier.init.shared.b64 [%0], %1;" :: "r"(m), "r"(cnt) : "memory");
}
__device__ __forceinline__ void mbar_expect_tx(u32 m, u32 bytes) {
    asm volatile("mbarrier.arrive.expect_tx.shared.b64 _, [%0], %1;" :: "r"(m), "r"(bytes) : "memory");
}
__device__ __forceinline__ void mbar_arrive(u32 m) {
    asm volatile("mbarrier.arrive.shared.b64 _, [%0];" :: "r"(m) : "memory");
}
__device__ __forceinline__ void mwait(u32 m, u32 parity) {
    asm volatile(
        "{\n\t.reg .pred P;\n"
        "W%=:\n\tmbarrier.try_wait.parity.acquire.cta.shared::cta.b64 P, [%0], %1, 0x989680;\n"
        "\t@P bra D%=;\n\tbra W%=;\nD%=:\n\t}" :: "r"(m), "r"(parity) : "memory");
}
__device__ __forceinline__ void bulk_g2s(u32 dst, const void* src, u32 bytes, u32 m) {
    asm volatile(
        "cp.async.bulk.shared::cluster.global.mbarrier::complete_tx::bytes [%0], [%1], %2, [%3];"
        :: "r"(dst), "l"((u64)__cvta_generic_to_global(src)), "r"(bytes), "r"(m) : "memory");
}
__device__ __forceinline__ void f_proxy() { asm volatile("fence.proxy.async;" ::: "memory"); }
__device__ __forceinline__ unsigned ld_acq(const unsigned* p) {
    unsigned v;
    asm volatile("ld.global.acquire.gpu.u32 %0, [%1];" : "=r"(v) : "l"(p));
    return v;
}
__device__ __forceinline__ void st_rel(unsigned* p, unsigned v) {
    asm volatile("st.release.gpu.global.u32 [%0], %1;" :: "l"(p), "r"(v) : "memory");
}
__device__ __forceinline__ void ldsm_x4(u32 (&r)[4], u32 addr) {
    asm volatile("ldmatrix.sync.aligned.m8n8.x4.shared.b16 {%0,%1,%2,%3}, [%4];"
                 : "=r"(r[0]), "=r"(r[1]), "=r"(r[2]), "=r"(r[3]) : "r"(addr));
}
__device__ __forceinline__ void mma_bf16(float (&d)[4], const u32 (&a)[4], const u32* b) {
    asm volatile(
        "mma.sync.aligned.m16n8k16.row.col.f32.bf16.bf16.f32 "
        "{%0,%1,%2,%3}, {%4,%5,%6,%7}, {%8,%9}, {%0,%1,%2,%3};"
        : "+f"(d[0]), "+f"(d[1]), "+f"(d[2]), "+f"(d[3])
        : "r"(a[0]), "r"(a[1]), "r"(a[2]), "r"(a[3]), "r"(b[0]), "r"(b[1]));
}
__device__ __forceinline__ void mma_fp16(float (&d)[4], const u32 (&a)[4], const u32* b) {
    asm volatile(
        "mma.sync.aligned.m16n8k16.row.col.f32.f16.f16.f32 "
        "{%0,%1,%2,%3}, {%4,%5,%6,%7}, {%8,%9}, {%0,%1,%2,%3};"
        : "+f"(d[0]), "+f"(d[1]), "+f"(d[2]), "+f"(d[3])
        : "r"(a[0]), "r"(a[1]), "r"(a[2]), "r"(a[3]), "r"(b[0]), "r"(b[1]));
}
__device__ __forceinline__ void split_bf16(float v, u16& h, u16& l) {
    __nv_bfloat16 hb = __float2bfloat16_rn(v);
    __nv_bfloat16 lb = __float2bfloat16_rn(v - __bfloat162float(hb));
    h = *(u16*)&hb; l = *(u16*)&lb;
}

// ---- init ------------------------------------------------------------------
__global__ void init_kernel() {
    int i = blockIdx.x * blockDim.x + threadIdx.x;   // 65536
    ((u32*)g_hh[0])[i] = 0u;
    ((u32*)g_hl[0])[i] = 0u;
    if (i < 128) g_flags[i] = 0u;
}

// ---- conversions to blocked swizzled images --------------------------------
// x A-image: [mt][kc(16)][128 rows x 64 k] fp16, row=128B, unit u -> u^(row&7)
__global__ void conv_x_kernel(const float* __restrict__ x) {
    size_t idx = (size_t)blockIdx.x * 256 + threadIdx.x;   // 16,777,216
    u32 m = (u32)(idx >> 7), ku = (u32)(idx & 127);
    const float4* src = (const float4*)(x + (size_t)m * 1024 + ku * 8);
    float4 a = src[0], b = src[1];
    float v[8] = {a.x, a.y, a.z, a.w, b.x, b.y, b.z, b.w};
    union { u16 s[8]; uint4 q; } F;
#pragma unroll
    for (int i = 0; i < 8; i++) {
        __half hv = __float2half_rn(v[i]);
        F.s[i] = *(u16*)&hv;
    }
    u32 mt = m >> 7, r = m & 127, kc = ku >> 3, uu = ku & 7;
    size_t off = ((size_t)(mt * 16 + kc) << 13) + (r << 6) + ((uu ^ (r & 7)) << 3);
    *(uint4*)(g_xf + off) = F.q;
}
// Wi B-image: [nt(32)][kc(16)][128 n x 64 k] fp16
__global__ void conv_wi_kernel(const float* __restrict__ W0, const float* __restrict__ W1,
                               const float* __restrict__ W2, const float* __restrict__ W3) {
    u32 idx = blockIdx.x * 256 + threadIdx.x;   // 524288
    u32 n = idx & 4095, ku = idx >> 12;
    const float* __restrict__ W = (n < 1024) ? W0 : (n < 2048) ? W1 : (n < 3072) ? W2 : W3;
    u32 col = n & 1023;
    union { u16 s[8]; uint4 q; } F;
#pragma unroll
    for (int i = 0; i < 8; i++) {
        __half hv = __float2half_rn(W[(size_t)(ku * 8 + i) * 1024 + col]);
        F.s[i] = *(u16*)&hv;
    }
    u32 nt = n >> 7, r = n & 127, kc = ku >> 3, uu = ku & 7;
    size_t off = ((size_t)(nt * 16 + kc) << 13) + (r << 6) + ((uu ^ (r & 7)) << 3);
    *(uint4*)(g_wif + off) = F.q;
}
// Wh B-image: [cb(128)][32 rows(j=g*8+(n&7)) x 1024 k] bf16 hi/lo, row=2048B
__global__ void conv_wh_kernel(const float* __restrict__ W0, const float* __restrict__ W1,
                               const float* __restrict__ W2, const float* __restrict__ W3) {
    u32 idx = blockIdx.x * 256 + threadIdx.x;   // 524288
    u32 n = idx & 1023, ku = (idx >> 10) & 127, g = idx >> 17;
    const float* __restrict__ W = (g == 0) ? W0 : (g == 1) ? W1 : (g == 2) ? W2 : W3;
    union { u16 s[8]; uint4 q; } H, L;
#pragma unroll
    for (int i = 0; i < 8; i++)
        split_bf16(W[(size_t)(ku * 8 + i) * 1024 + n], H.s[i], L.s[i]);
    u32 cb = n >> 3, j = g * 8 + (n & 7);
    size_t off = ((size_t)cb << 15) + (j << 10) + ((ku ^ (j & 7)) << 3);
    *(uint4*)(g_whh + off) = H.q;
    *(uint4*)(g_whl + off) = L.q;
}

// ---- Phase 1: x_proj = x @ Wi + bias. fp16 MMA (R8-proven) -----------------
__global__ void __launch_bounds__(256, 1) xproj_mma(
    const float* __restrict__ b_i, const float* __restrict__ b_f,
    const float* __restrict__ b_g, const float* __restrict__ b_o)
{
    extern __shared__ __align__(1024) char smem[];
    const u32 sb = sptr(smem);
    const int tid = threadIdx.x, lane = tid & 31, w = tid >> 5;
    const int bx = blockIdx.x, by = blockIdx.y;
    const u32 SA = sb + 1024, SBB = sb + 33792;

    if (tid == 0) {
        mbar_init(sb + 0, 1);   mbar_init(sb + 8, 1);     // full
        mbar_init(sb + 16, 256); mbar_init(sb + 24, 256); // empty
    }
    __syncthreads();

    const char* ax = (const char*)g_xf + (size_t)by * 262144;
    const char* bw = (const char*)g_wif + (size_t)bx * 262144;

    auto issue = [&](int c) {
        int buf = c & 1;
        mwait(sb + 16 + buf * 8, ((c >> 1) & 1) ^ 1);
        mbar_expect_tx(sb + buf * 8, 32768);
        bulk_g2s(SA + buf * 16384,  ax + (size_t)c * 16384, 16384, sb + buf * 8);
        bulk_g2s(SBB + buf * 16384, bw + (size_t)c * 16384, 16384, sb + buf * 8);
    };
    if (tid == 0) { issue(0); issue(1); }

    const int wr = w >> 2, wc = w & 3;
    const int arow = (lane & 7) + ((lane >> 3) & 1) * 8;
    const int aub  = lane >> 4;
    const int brow = (lane & 7) + (lane >> 4) * 8;
    const int bub  = (lane >> 3) & 1;

    float acc[4][4][4];
#pragma unroll
    for (int i = 0; i < 4; i++)
#pragma unroll
        for (int j = 0; j < 4; j++)
#pragma unroll
            for (int q = 0; q < 4; q++) acc[i][j][q] = 0.f;

    for (int c = 0; c < 16; c++) {
        int buf = c & 1;
        mwait(sb + buf * 8, (c >> 1) & 1);
        u32 Ab = SA + buf * 16384, Bb = SBB + buf * 16384;
#pragma unroll
        for (int s = 0; s < 4; s++) {
            u32 a4[4][4];
#pragma unroll
            for (int mt = 0; mt < 4; mt++) {
                int r = wr * 64 + mt * 16 + arow;
                u32 off = (u32)(r * 128 + (((s * 2 + aub) ^ (r & 7)) << 4));
                ldsm_x4(a4[mt], Ab + off);
            }
#pragma unroll
            for (int np = 0; np < 2; np++) {
                int n = wc * 32 + np * 16 + brow;
                u32 off = (u32)(n * 128 + (((s * 2 + bub) ^ (n & 7)) << 4));
                u32 b4[4];
                ldsm_x4(b4, Bb + off);
#pragma unroll
                for (int mt = 0; mt < 4; mt++) {
                    mma_fp16(acc[mt][np * 2 + 0], a4[mt], b4 + 0);
                    mma_fp16(acc[mt][np * 2 + 1], a4[mt], b4 + 2);
                }
            }
        }
        mbar_arrive(sb + 16 + buf * 8);
        if (tid == 0 && c < 14) issue(c + 2);
    }

    const int gate = bx >> 3;
    const float* __restrict__ bias =
        (gate == 0) ? b_i : (gate == 1) ? b_f : (gate == 2) ? b_g : b_o;
    const int bcol0 = (bx & 7) * 128 + wc * 32 + (lane & 3) * 2;
    float2 bv[4];
#pragma unroll
    for (int nt = 0; nt < 4; nt++)
        bv[nt] = make_float2(bias[bcol0 + nt * 8], bias[bcol0 + nt * 8 + 1]);

    const int colg = bx * 128 + wc * 32 + (lane & 3) * 2;
#pragma unroll
    for (int mt = 0; mt < 4; mt++) {
#pragma unroll
        for (int h2 = 0; h2 < 2; h2++) {
            int m = by * 128 + wr * 64 + mt * 16 + (lane >> 2) + h2 * 8;
            int bb = m >> 10, t = m & 1023;
            float* __restrict__ xp =
                ((t < 512) ? g_xp0 : g_xp1) + ((size_t)(t & 511) * 128 + bb) * 4096 + colg;
#pragma unroll
            for (int nt = 0; nt < 4; nt++) {
                float2 o = make_float2(acc[mt][nt][h2 * 2 + 0] + bv[nt].x,
                                       acc[mt][nt][h2 * 2 + 1] + bv[nt].y);
                *(float2*)(xp + nt * 8) = o;
            }
        }
    }
}

// ---- Phase 2 (persistent, R8 mainloop): 128 CTAs x 256 thr -----------------
// Step boundary: distributed flags (one st.release per CTA, 128 parallel
// pollers) + early prefetch of chunks 0,1 gated on their 8-CTA producer groups
// via two small mbarriers, so TMA refill overlaps the barrier tail.
__global__ void __launch_bounds__(256, 1) lstm_mma(float* __restrict__ out)
{
    extern __shared__ __align__(1024) char smem[];
    const u32 sb = sptr(smem);
    const int tid = threadIdx.x, lane = tid & 31, w = tid >> 5;
    const int cb = blockIdx.x;
    const u32 SBH = sb + 1024, SBL = sb + 66560, SA = sb + 132096;
    const u32 EARLY0 = sb + 40, EARLY1 = sb + 48;

    if (tid == 0) {
        mbar_init(sb + 0, 1);   mbar_init(sb + 8, 1);     // full
        mbar_init(sb + 16, 256); mbar_init(sb + 24, 256); // empty
        mbar_init(sb + 32, 1);                            // Wh
        mbar_init(EARLY0, 8);  mbar_init(EARLY1, 8);      // early chunk gates
        mbar_expect_tx(sb + 32, 131072);
        bulk_g2s(SBH, (const char*)g_whh + (size_t)cb * 65536, 65536, sb + 32);
        bulk_g2s(SBL, (const char*)g_whl + (size_t)cb * 65536, 65536, sb + 32);
    }
    __syncthreads();
    mwait(sb + 32, 0);

    const int arow = (lane & 7) + ((lane >> 3) & 1) * 8;
    const int aub  = lane >> 4;
    const int brow = (lane & 7) + (lane >> 4) * 8;
    const int bub  = (lane >> 3) & 1;
    const int r0 = w * 16 + (lane >> 2), p = lane & 3;
    const u32 aoff_base = (u32)((w * 16 + arow) * 128);
    const int ar7 = (w * 16 + arow) & 7;

    auto issue = [&](int t, int c) {
        int buf = c & 1;
        mwait(sb + 16 + buf * 8, ((c >> 1) & 1) ^ 1);
        mbar_expect_tx(sb + buf * 8, 32768);
        const char* hh = (const char*)g_hh[t & 1] + (size_t)c * 16384;
        const char* hl = (const char*)g_hl[t & 1] + (size_t)c * 16384;
        bulk_g2s(SA + buf * 32768,          hh, 16384, sb + buf * 8);
        bulk_g2s(SA + buf * 32768 + 16384,  hl, 16384, sb + buf * 8);
    };

    float cst[2][2] = {{0.f, 0.f}, {0.f, 0.f}};

    for (int t = 0; t < TT; t++) {
        if (t == 0 && tid == 0) { f_proxy(); issue(0, 0); issue(0, 1); }

        // prefetch xp gate values for this thread's 4 outputs (hide L2 latency)
        const float* xpb = ((t < 512) ? g_xp0 : g_xp1) + (size_t)(t & 511) * 524288;
        float2 xg[2][4];
#pragma unroll
        for (int half = 0; half < 2; half++) {
            const float* xr = xpb + (size_t)(r0 + half * 8) * 4096 + cb * 8 + p * 2;
            xg[half][0] = *(const float2*)(xr);
            xg[half][1] = *(const float2*)(xr + 1024);
            xg[half][2] = *(const float2*)(xr + 2048);
            xg[half][3] = *(const float2*)(xr + 3072);
        }

        float acc[4][4];
#pragma unroll
        for (int i = 0; i < 4; i++)
#pragma unroll
            for (int q = 0; q < 4; q++) acc[i][q] = 0.f;

        for (int c = 0; c < 16; c++) {
            int buf = c & 1;
            mwait(sb + buf * 8, (c >> 1) & 1);
            u32 Ah = SA + buf * 32768, Al = Ah + 16384;
#pragma unroll
            for (int s = 0; s < 4; s++) {
                u32 ah[4], al[4];
                u32 aoff = aoff_base + (((s * 2 + aub) ^ ar7) << 4);
                ldsm_x4(ah, Ah + aoff);
                ldsm_x4(al, Al + aoff);
                int kk2 = (c * 4 + s) * 2 + bub;
#pragma unroll
                for (int np = 0; np < 2; np++) {
                    int j = np * 16 + brow;
                    u32 boff = (u32)(j * 2048 + ((kk2 ^ (j & 7)) << 4));
                    u32 bh[4], bl[4];
                    ldsm_x4(bh, SBH + boff);
                    ldsm_x4(bl, SBL + boff);
                    mma_bf16(acc[np * 2 + 0], ah, bh + 0);
                    mma_bf16(acc[np * 2 + 0], ah, bl + 0);
                    mma_bf16(acc[np * 2 + 0], al, bh + 0);
                    mma_bf16(acc[np * 2 + 1], ah, bh + 2);
                    mma_bf16(acc[np * 2 + 1], ah, bl + 2);
                    mma_bf16(acc[np * 2 + 1], al, bh + 2);
                }
            }
            mbar_arrive(sb + 16 + buf * 8);
            if (tid == 0 && c < 14) issue(t, c + 2);
        }

        // epilogue: acc[0..3] = gates i,f,g,o at cols jj=2p,2p+1; rows r0, r0+8
        float hv[2][2];
#pragma unroll
        for (int half = 0; half < 2; half++) {
            int b = r0 + half * 8;
#pragma unroll
            for (int q = 0; q < 2; q++) {
                float iv = acc[0][half * 2 + q] + (q ? xg[half][0].y : xg[half][0].x);
                float fv = acc[1][half * 2 + q] + (q ? xg[half][1].y : xg[half][1].x);
                float gv = acc[2][half * 2 + q] + (q ? xg[half][2].y : xg[half][2].x);
                float ov = acc[3][half * 2 + q] + (q ? xg[half][3].y : xg[half][3].x);
                float si = 1.f / (1.f + expf(-iv));
                float sf = 1.f / (1.f + expf(-fv));
                float tg = tanhf(gv);
                float so = 1.f / (1.f + expf(-ov));
                cst[half][q] = sf * cst[half][q] + si * tg;
                hv[half][q] = so * tanhf(cst[half][q]);
            }
            u16 h0, l0, h1, l1;
            split_bf16(hv[half][0], h0, l0);
            split_bf16(hv[half][1], h1, l1);
            u32 hw = (u32)h0 | ((u32)h1 << 16);
            u32 lw = (u32)l0 | ((u32)l1 << 16);
            u32 off = (u32)(cb >> 3) * 16384 + (u32)b * 128
                    + (u32)(((cb & 7) ^ (b & 7)) << 4) + (u32)p * 4;
            *(u32*)((char*)g_hh[(t + 1) & 1] + off) = hw;
            *(u32*)((char*)g_hl[(t + 1) & 1] + off) = lw;
        }

        if (t == TT - 1) {
#pragma unroll
            for (int half = 0; half < 2; half++) {
                int b = r0 + half * 8;
                float* o1 = out + (size_t)b * 1024 + cb * 8 + p * 2;
                o1[0] = hv[half][0]; o1[1] = hv[half][1];
                float* o2 = o1 + 131072;
                o2[0] = cst[half][0]; o2[1] = cst[half][1];
            }
        }

        if (t < TT - 1) {   // distributed-flag barrier + early refill
            __syncthreads();
            if (tid == 0) {
                __threadfence();
                st_rel(&g_flags[cb], (unsigned)(t + 1));
            }
            if (tid < 128) {
                unsigned tgt = (unsigned)(t + 1);
                while (ld_acq(&g_flags[tid]) < tgt) {}
                if (tid < 8)       mbar_arrive(EARLY0);
                else if (tid < 16) mbar_arrive(EARLY1);
            }
            if (tid == 0) {
                mwait(EARLY0, t & 1);      // chunk-0 producers (CTAs 0..7) done
                f_proxy();
                issue(t + 1, 0);
                mwait(EARLY1, t & 1);      // chunk-1 producers (CTAs 8..15) done
                issue(t + 1, 1);
            }
            __syncthreads();
        }
    }
}

// ---------------------------------------------------------------------------
extern "C" void kernel_launch(void* const* d_in, const int* in_sizes, int n_in,
                              void* d_out, int out_size)
{
    const float* x   = (const float*)d_in[0];
    const float* Wii = (const float*)d_in[1];
    const float* Wif = (const float*)d_in[2];
    const float* Wig = (const float*)d_in[3];
    const float* Wio = (const float*)d_in[4];
    const float* Whi = (const float*)d_in[5];
    const float* Whf = (const float*)d_in[6];
    const float* Whg = (const float*)d_in[7];
    const float* Who = (const float*)d_in[8];
    const float* b_i = (const float*)d_in[9];
    const float* b_f = (const float*)d_in[10];
    const float* b_g = (const float*)d_in[11];
    const float* b_o = (const float*)d_in[12];
    float* out = (float*)d_out;

    cudaFuncSetAttribute(xproj_mma, cudaFuncAttributeMaxDynamicSharedMemorySize, 66560);
    cudaFuncSetAttribute(lstm_mma,  cudaFuncAttributeMaxDynamicSharedMemorySize, 197632);

    init_kernel<<<256, 256>>>();
    conv_x_kernel<<<65536, 256>>>(x);
    conv_wi_kernel<<<2048, 256>>>(Wii, Wif, Wig, Wio);
    conv_wh_kernel<<<2048, 256>>>(Whi, Whf, Whg, Who);

    dim3 g1(32, 1024);
    xproj_mma<<<g1, 256, 66560>>>(b_i, b_f, b_g, b_o);
    lstm_mma<<<128, 256, 197632>>>(out);
}

// round 12
// speedup vs baseline: 1.3759x; 1.3759x over previous
#include <cuda_runtime.h>
#include <cuda_bf16.h>
#include <cuda_fp16.h>

typedef unsigned int u32;
typedef unsigned long long u64;
typedef unsigned short u16;

#define TT 1024

// ---- device scratch --------------------------------------------------------
__device__ __align__(1024) float g_xp0[(size_t)512 * 128 * 4096];
__device__ __align__(1024) float g_xp1[(size_t)512 * 128 * 4096];
__device__ __align__(1024) __half g_xf[(size_t)128 * 1024 * 1024];   // x fp16 A-image
__device__ __align__(1024) __half g_wif[(size_t)4096 * 1024];        // Wi fp16 B-image
__device__ __align__(1024) __nv_bfloat16 g_whh[(size_t)4096 * 1024]; // Wh bf16 hi
__device__ __align__(1024) __nv_bfloat16 g_whl[(size_t)4096 * 1024]; // Wh bf16 lo
// h images ping-pong: 16 chunks x [128 b x 64 k], 128B rows, unit u -> u^(b&7)
__device__ __align__(1024) __nv_bfloat16 g_hh[2][16 * 128 * 64];
__device__ __align__(1024) __nv_bfloat16 g_hl[2][16 * 128 * 64];
// two-level barrier: 8 group counters (256B apart) + root at [512]
__device__ __align__(1024) unsigned g_bar2[1024];

// ---- PTX helpers (base sm_103 safe) ---------------------------------------
__device__ __forceinline__ u32 sptr(const void* p) {
    u32 a;
    asm("{ .reg .u64 t; cvta.to.shared.u64 t, %1; cvt.u32.u64 %0, t; }" : "=r"(a) : "l"(p));
    return a;
}
__device__ __forceinline__ void mbar_init(u32 m, u32 cnt) {
    asm volatile("mbarrier.init.shared.b64 [%0], %1;" :: "r"(m), "r"(cnt) : "memory");
}
__device__ __forceinline__ void mbar_expect_tx(u32 m, u32 bytes) {
    asm volatile("mbarrier.arrive.expect_tx.shared.b64 _, [%0], %1;" :: "r"(m), "r"(bytes) : "memory");
}
__device__ __forceinline__ void mbar_arrive(u32 m) {
    asm volatile("mbarrier.arrive.shared.b64 _, [%0];" :: "r"(m) : "memory");
}
__device__ __forceinline__ void mwait(u32 m, u32 parity) {
    asm volatile(
        "{\n\t.reg .pred P;\n"
        "W%=:\n\tmbarrier.try_wait.parity.acquire.cta.shared::cta.b64 P, [%0], %1, 0x989680;\n"
        "\t@P bra D%=;\n\tbra W%=;\nD%=:\n\t}" :: "r"(m), "r"(parity) : "memory");
}
__device__ __forceinline__ void bulk_g2s(u32 dst, const void* src, u32 bytes, u32 m) {
    asm volatile(
        "cp.async.bulk.shared::cluster.global.mbarrier::complete_tx::bytes [%0], [%1], %2, [%3];"
        :: "r"(dst), "l"((u64)__cvta_generic_to_global(src)), "r"(bytes), "r"(m) : "memory");
}
__device__ __forceinline__ void f_proxy() { asm volatile("fence.proxy.async;" ::: "memory"); }
__device__ __forceinline__ unsigned ld_acq(const unsigned* p) {
    unsigned v;
    asm volatile("ld.global.acquire.gpu.u32 %0, [%1];" : "=r"(v) : "l"(p));
    return v;
}
__device__ __forceinline__ void ldsm_x4(u32 (&r)[4], u32 addr) {
    asm volatile("ldmatrix.sync.aligned.m8n8.x4.shared.b16 {%0,%1,%2,%3}, [%4];"
                 : "=r"(r[0]), "=r"(r[1]), "=r"(r[2]), "=r"(r[3]) : "r"(addr));
}
__device__ __forceinline__ void mma_bf16(float (&d)[4], const u32 (&a)[4], const u32* b) {
    asm volatile(
        "mma.sync.aligned.m16n8k16.row.col.f32.bf16.bf16.f32 "
        "{%0,%1,%2,%3}, {%4,%5,%6,%7}, {%8,%9}, {%0,%1,%2,%3};"
        : "+f"(d[0]), "+f"(d[1]), "+f"(d[2]), "+f"(d[3])
        : "r"(a[0]), "r"(a[1]), "r"(a[2]), "r"(a[3]), "r"(b[0]), "r"(b[1]));
}
__device__ __forceinline__ void mma_fp16(float (&d)[4], const u32 (&a)[4], const u32* b) {
    asm volatile(
        "mma.sync.aligned.m16n8k16.row.col.f32.f16.f16.f32 "
        "{%0,%1,%2,%3}, {%4,%5,%6,%7}, {%8,%9}, {%0,%1,%2,%3};"
        : "+f"(d[0]), "+f"(d[1]), "+f"(d[2]), "+f"(d[3])
        : "r"(a[0]), "r"(a[1]), "r"(a[2]), "r"(a[3]), "r"(b[0]), "r"(b[1]));
}
__device__ __forceinline__ void split_bf16(float v, u16& h, u16& l) {
    __nv_bfloat16 hb = __float2bfloat16_rn(v);
    __nv_bfloat16 lb = __float2bfloat16_rn(v - __bfloat162float(hb));
    h = *(u16*)&hb; l = *(u16*)&lb;
}

// ---- init ------------------------------------------------------------------
__global__ void init_kernel() {
    int i = blockIdx.x * blockDim.x + threadIdx.x;   // 65536
    ((u32*)g_hh[0])[i] = 0u;
    ((u32*)g_hl[0])[i] = 0u;
    if (i < 1024) g_bar2[i] = 0u;
}

// ---- conversions to blocked swizzled images --------------------------------
// x A-image: [mt][kc(16)][128 rows x 64 k] fp16, row=128B, unit u -> u^(row&7)
__global__ void conv_x_kernel(const float* __restrict__ x) {
    size_t idx = (size_t)blockIdx.x * 256 + threadIdx.x;   // 16,777,216
    u32 m = (u32)(idx >> 7), ku = (u32)(idx & 127);
    const float4* src = (const float4*)(x + (size_t)m * 1024 + ku * 8);
    float4 a = src[0], b = src[1];
    float v[8] = {a.x, a.y, a.z, a.w, b.x, b.y, b.z, b.w};
    union { u16 s[8]; uint4 q; } F;
#pragma unroll
    for (int i = 0; i < 8; i++) {
        __half hv = __float2half_rn(v[i]);
        F.s[i] = *(u16*)&hv;
    }
    u32 mt = m >> 7, r = m & 127, kc = ku >> 3, uu = ku & 7;
    size_t off = ((size_t)(mt * 16 + kc) << 13) + (r << 6) + ((uu ^ (r & 7)) << 3);
    *(uint4*)(g_xf + off) = F.q;
}
// Wi B-image: [nt(32)][kc(16)][128 n x 64 k] fp16
__global__ void conv_wi_kernel(const float* __restrict__ W0, const float* __restrict__ W1,
                               const float* __restrict__ W2, const float* __restrict__ W3) {
    u32 idx = blockIdx.x * 256 + threadIdx.x;   // 524288
    u32 n = idx & 4095, ku = idx >> 12;
    const float* __restrict__ W = (n < 1024) ? W0 : (n < 2048) ? W1 : (n < 3072) ? W2 : W3;
    u32 col = n & 1023;
    union { u16 s[8]; uint4 q; } F;
#pragma unroll
    for (int i = 0; i < 8; i++) {
        __half hv = __float2half_rn(W[(size_t)(ku * 8 + i) * 1024 + col]);
        F.s[i] = *(u16*)&hv;
    }
    u32 nt = n >> 7, r = n & 127, kc = ku >> 3, uu = ku & 7;
    size_t off = ((size_t)(nt * 16 + kc) << 13) + (r << 6) + ((uu ^ (r & 7)) << 3);
    *(uint4*)(g_wif + off) = F.q;
}
// Wh B-image: [cb(128)][32 rows(j=g*8+(n&7)) x 1024 k] bf16 hi/lo, row=2048B
__global__ void conv_wh_kernel(const float* __restrict__ W0, const float* __restrict__ W1,
                               const float* __restrict__ W2, const float* __restrict__ W3) {
    u32 idx = blockIdx.x * 256 + threadIdx.x;   // 524288
    u32 n = idx & 1023, ku = (idx >> 10) & 127, g = idx >> 17;
    const float* __restrict__ W = (g == 0) ? W0 : (g == 1) ? W1 : (g == 2) ? W2 : W3;
    union { u16 s[8]; uint4 q; } H, L;
#pragma unroll
    for (int i = 0; i < 8; i++)
        split_bf16(W[(size_t)(ku * 8 + i) * 1024 + n], H.s[i], L.s[i]);
    u32 cb = n >> 3, j = g * 8 + (n & 7);
    size_t off = ((size_t)cb << 15) + (j << 10) + ((ku ^ (j & 7)) << 3);
    *(uint4*)(g_whh + off) = H.q;
    *(uint4*)(g_whl + off) = L.q;
}

// ---- Phase 1: x_proj = x @ Wi + bias. fp16 MMA (R8-proven) -----------------
__global__ void __launch_bounds__(256, 1) xproj_mma(
    const float* __restrict__ b_i, const float* __restrict__ b_f,
    const float* __restrict__ b_g, const float* __restrict__ b_o)
{
    extern __shared__ __align__(1024) char smem[];
    const u32 sb = sptr(smem);
    const int tid = threadIdx.x, lane = tid & 31, w = tid >> 5;
    const int bx = blockIdx.x, by = blockIdx.y;
    const u32 SA = sb + 1024, SBB = sb + 33792;

    if (tid == 0) {
        mbar_init(sb + 0, 1);   mbar_init(sb + 8, 1);     // full
        mbar_init(sb + 16, 256); mbar_init(sb + 24, 256); // empty
    }
    __syncthreads();

    const char* ax = (const char*)g_xf + (size_t)by * 262144;
    const char* bw = (const char*)g_wif + (size_t)bx * 262144;

    auto issue = [&](int c) {
        int buf = c & 1;
        mwait(sb + 16 + buf * 8, ((c >> 1) & 1) ^ 1);
        mbar_expect_tx(sb + buf * 8, 32768);
        bulk_g2s(SA + buf * 16384,  ax + (size_t)c * 16384, 16384, sb + buf * 8);
        bulk_g2s(SBB + buf * 16384, bw + (size_t)c * 16384, 16384, sb + buf * 8);
    };
    if (tid == 0) { issue(0); issue(1); }

    const int wr = w >> 2, wc = w & 3;
    const int arow = (lane & 7) + ((lane >> 3) & 1) * 8;
    const int aub  = lane >> 4;
    const int brow = (lane & 7) + (lane >> 4) * 8;
    const int bub  = (lane >> 3) & 1;

    float acc[4][4][4];
#pragma unroll
    for (int i = 0; i < 4; i++)
#pragma unroll
        for (int j = 0; j < 4; j++)
#pragma unroll
            for (int q = 0; q < 4; q++) acc[i][j][q] = 0.f;

    for (int c = 0; c < 16; c++) {
        int buf = c & 1;
        mwait(sb + buf * 8, (c >> 1) & 1);
        u32 Ab = SA + buf * 16384, Bb = SBB + buf * 16384;
#pragma unroll
        for (int s = 0; s < 4; s++) {
            u32 a4[4][4];
#pragma unroll
            for (int mt = 0; mt < 4; mt++) {
                int r = wr * 64 + mt * 16 + arow;
                u32 off = (u32)(r * 128 + (((s * 2 + aub) ^ (r & 7)) << 4));
                ldsm_x4(a4[mt], Ab + off);
            }
#pragma unroll
            for (int np = 0; np < 2; np++) {
                int n = wc * 32 + np * 16 + brow;
                u32 off = (u32)(n * 128 + (((s * 2 + bub) ^ (n & 7)) << 4));
                u32 b4[4];
                ldsm_x4(b4, Bb + off);
#pragma unroll
                for (int mt = 0; mt < 4; mt++) {
                    mma_fp16(acc[mt][np * 2 + 0], a4[mt], b4 + 0);
                    mma_fp16(acc[mt][np * 2 + 1], a4[mt], b4 + 2);
                }
            }
        }
        mbar_arrive(sb + 16 + buf * 8);
        if (tid == 0 && c < 14) issue(c + 2);
    }

    const int gate = bx >> 3;
    const float* __restrict__ bias =
        (gate == 0) ? b_i : (gate == 1) ? b_f : (gate == 2) ? b_g : b_o;
    const int bcol0 = (bx & 7) * 128 + wc * 32 + (lane & 3) * 2;
    float2 bv[4];
#pragma unroll
    for (int nt = 0; nt < 4; nt++)
        bv[nt] = make_float2(bias[bcol0 + nt * 8], bias[bcol0 + nt * 8 + 1]);

    const int colg = bx * 128 + wc * 32 + (lane & 3) * 2;
#pragma unroll
    for (int mt = 0; mt < 4; mt++) {
#pragma unroll
        for (int h2 = 0; h2 < 2; h2++) {
            int m = by * 128 + wr * 64 + mt * 16 + (lane >> 2) + h2 * 8;
            int bb = m >> 10, t = m & 1023;
            float* __restrict__ xp =
                ((t < 512) ? g_xp0 : g_xp1) + ((size_t)(t & 511) * 128 + bb) * 4096 + colg;
#pragma unroll
            for (int nt = 0; nt < 4; nt++) {
                float2 o = make_float2(acc[mt][nt][h2 * 2 + 0] + bv[nt].x,
                                       acc[mt][nt][h2 * 2 + 1] + bv[nt].y);
                *(float2*)(xp + nt * 8) = o;
            }
        }
    }
}

// ---- Phase 2 (persistent, R8 mainloop): 128 CTAs x 256 thr -----------------
// Two-level barrier: 8 group counters (16 arrivals each, distinct L2 lines)
// + root counter (8 arrivals) -> arrival serialization ~770cyc vs ~4096cyc.
__global__ void __launch_bounds__(256, 1) lstm_mma(float* __restrict__ out)
{
    extern __shared__ __align__(1024) char smem[];
    const u32 sb = sptr(smem);
    const int tid = threadIdx.x, lane = tid & 31, w = tid >> 5;
    const int cb = blockIdx.x;
    const u32 SBH = sb + 1024, SBL = sb + 66560, SA = sb + 132096;

    if (tid == 0) {
        mbar_init(sb + 0, 1);   mbar_init(sb + 8, 1);     // full
        mbar_init(sb + 16, 256); mbar_init(sb + 24, 256); // empty
        mbar_init(sb + 32, 1);                            // Wh
        mbar_expect_tx(sb + 32, 131072);
        bulk_g2s(SBH, (const char*)g_whh + (size_t)cb * 65536, 65536, sb + 32);
        bulk_g2s(SBL, (const char*)g_whl + (size_t)cb * 65536, 65536, sb + 32);
    }
    __syncthreads();
    mwait(sb + 32, 0);

    const int arow = (lane & 7) + ((lane >> 3) & 1) * 8;
    const int aub  = lane >> 4;
    const int brow = (lane & 7) + (lane >> 4) * 8;
    const int bub  = (lane >> 3) & 1;
    const int r0 = w * 16 + (lane >> 2), p = lane & 3;
    const u32 aoff_base = (u32)((w * 16 + arow) * 128);
    const int ar7 = (w * 16 + arow) & 7;

    auto issue = [&](int t, int c) {
        int buf = c & 1;
        mwait(sb + 16 + buf * 8, ((c >> 1) & 1) ^ 1);
        mbar_expect_tx(sb + buf * 8, 32768);
        const char* hh = (const char*)g_hh[t & 1] + (size_t)c * 16384;
        const char* hl = (const char*)g_hl[t & 1] + (size_t)c * 16384;
        bulk_g2s(SA + buf * 32768,          hh, 16384, sb + buf * 8);
        bulk_g2s(SA + buf * 32768 + 16384,  hl, 16384, sb + buf * 8);
    };

    float cst[2][2] = {{0.f, 0.f}, {0.f, 0.f}};

    for (int t = 0; t < TT; t++) {
        if (tid == 0) { f_proxy(); issue(t, 0); issue(t, 1); }

        // prefetch xp gate values for this thread's 4 outputs (hide L2 latency)
        const float* xpb = ((t < 512) ? g_xp0 : g_xp1) + (size_t)(t & 511) * 524288;
        float2 xg[2][4];
#pragma unroll
        for (int half = 0; half < 2; half++) {
            const float* xr = xpb + (size_t)(r0 + half * 8) * 4096 + cb * 8 + p * 2;
            xg[half][0] = *(const float2*)(xr);
            xg[half][1] = *(const float2*)(xr + 1024);
            xg[half][2] = *(const float2*)(xr + 2048);
            xg[half][3] = *(const float2*)(xr + 3072);
        }

        float acc[4][4];
#pragma unroll
        for (int i = 0; i < 4; i++)
#pragma unroll
            for (int q = 0; q < 4; q++) acc[i][q] = 0.f;

        for (int c = 0; c < 16; c++) {
            int buf = c & 1;
            mwait(sb + buf * 8, (c >> 1) & 1);
            u32 Ah = SA + buf * 32768, Al = Ah + 16384;
#pragma unroll
            for (int s = 0; s < 4; s++) {
                u32 ah[4], al[4];
                u32 aoff = aoff_base + (((s * 2 + aub) ^ ar7) << 4);
                ldsm_x4(ah, Ah + aoff);
                ldsm_x4(al, Al + aoff);
                int kk2 = (c * 4 + s) * 2 + bub;
#pragma unroll
                for (int np = 0; np < 2; np++) {
                    int j = np * 16 + brow;
                    u32 boff = (u32)(j * 2048 + ((kk2 ^ (j & 7)) << 4));
                    u32 bh[4], bl[4];
                    ldsm_x4(bh, SBH + boff);
                    ldsm_x4(bl, SBL + boff);
                    mma_bf16(acc[np * 2 + 0], ah, bh + 0);
                    mma_bf16(acc[np * 2 + 0], ah, bl + 0);
                    mma_bf16(acc[np * 2 + 0], al, bh + 0);
                    mma_bf16(acc[np * 2 + 1], ah, bh + 2);
                    mma_bf16(acc[np * 2 + 1], ah, bl + 2);
                    mma_bf16(acc[np * 2 + 1], al, bh + 2);
                }
            }
            mbar_arrive(sb + 16 + buf * 8);
            if (tid == 0 && c < 14) issue(t, c + 2);
        }

        // epilogue: acc[0..3] = gates i,f,g,o at cols jj=2p,2p+1; rows r0, r0+8
        float hv[2][2];
#pragma unroll
        for (int half = 0; half < 2; half++) {
            int b = r0 + half * 8;
#pragma unroll
            for (int q = 0; q < 2; q++) {
                float iv = acc[0][half * 2 + q] + (q ? xg[half][0].y : xg[half][0].x);
                float fv = acc[1][half * 2 + q] + (q ? xg[half][1].y : xg[half][1].x);
                float gv = acc[2][half * 2 + q] + (q ? xg[half][2].y : xg[half][2].x);
                float ov = acc[3][half * 2 + q] + (q ? xg[half][3].y : xg[half][3].x);
                float si = 1.f / (1.f + expf(-iv));
                float sf = 1.f / (1.f + expf(-fv));
                float tg = tanhf(gv);
                float so = 1.f / (1.f + expf(-ov));
                cst[half][q] = sf * cst[half][q] + si * tg;
                hv[half][q] = so * tanhf(cst[half][q]);
            }
            u16 h0, l0, h1, l1;
            split_bf16(hv[half][0], h0, l0);
            split_bf16(hv[half][1], h1, l1);
            u32 hw = (u32)h0 | ((u32)h1 << 16);
            u32 lw = (u32)l0 | ((u32)l1 << 16);
            u32 off = (u32)(cb >> 3) * 16384 + (u32)b * 128
                    + (u32)(((cb & 7) ^ (b & 7)) << 4) + (u32)p * 4;
            *(u32*)((char*)g_hh[(t + 1) & 1] + off) = hw;
            *(u32*)((char*)g_hl[(t + 1) & 1] + off) = lw;
        }

        if (t == TT - 1) {
#pragma unroll
            for (int half = 0; half < 2; half++) {
                int b = r0 + half * 8;
                float* o1 = out + (size_t)b * 1024 + cb * 8 + p * 2;
                o1[0] = hv[half][0]; o1[1] = hv[half][1];
                float* o2 = o1 + 131072;
                o2[0] = cst[half][0]; o2[1] = cst[half][1];
            }
        }

        if (t < TT - 1) {   // two-level global barrier
            __syncthreads();
            if (tid == 0) {
                __threadfence();
                unsigned old = atomicAdd(&g_bar2[(cb & 7) * 64], 1u);
                if (old == 16u * (unsigned)(t + 1) - 1u) {
                    __threadfence();
                    atomicAdd(&g_bar2[512], 1u);
                }
                unsigned tgt = 8u * (unsigned)(t + 1);
                while (ld_acq(&g_bar2[512]) < tgt) __nanosleep(32);
            }
            __syncthreads();
        }
    }
}

// ---------------------------------------------------------------------------
extern "C" void kernel_launch(void* const* d_in, const int* in_sizes, int n_in,
                              void* d_out, int out_size)
{
    const float* x   = (const float*)d_in[0];
    const float* Wii = (const float*)d_in[1];
    const float* Wif = (const float*)d_in[2];
    const float* Wig = (const float*)d_in[3];
    const float* Wio = (const float*)d_in[4];
    const float* Whi = (const float*)d_in[5];
    const float* Whf = (const float*)d_in[6];
    const float* Whg = (const float*)d_in[7];
    const float* Who = (const float*)d_in[8];
    const float* b_i = (const float*)d_in[9];
    const float* b_f = (const float*)d_in[10];
    const float* b_g = (const float*)d_in[11];
    const float* b_o = (const float*)d_in[12];
    float* out = (float*)d_out;

    cudaFuncSetAttribute(xproj_mma, cudaFuncAttributeMaxDynamicSharedMemorySize, 66560);
    cudaFuncSetAttribute(lstm_mma,  cudaFuncAttributeMaxDynamicSharedMemorySize, 197632);

    init_kernel<<<256, 256>>>();
    conv_x_kernel<<<65536, 256>>>(x);
    conv_wi_kernel<<<2048, 256>>>(Wii, Wif, Wig, Wio);
    conv_wh_kernel<<<2048, 256>>>(Whi, Whf, Whg, Who);

    dim3 g1(32, 1024);
    xproj_mma<<<g1, 256, 66560>>>(b_i, b_f, b_g, b_o);
    lstm_mma<<<128, 256, 197632>>>(out);
}

// round 14
// speedup vs baseline: 1.6182x; 1.1761x over previous
#include <cuda_runtime.h>
#include <cuda_bf16.h>
#include <cuda_fp16.h>

typedef unsigned int u32;
typedef unsigned long long u64;
typedef unsigned short u16;

#define TT 1024

// ---- device scratch --------------------------------------------------------
__device__ __align__(1024) float g_xp0[(size_t)512 * 128 * 4096];
__device__ __align__(1024) float g_xp1[(size_t)512 * 128 * 4096];
__device__ __align__(1024) __half g_xf[(size_t)128 * 1024 * 1024];   // x fp16 A-image
__device__ __align__(1024) __half g_wif[(size_t)4096 * 1024];        // Wi fp16 B-image
__device__ __align__(1024) __half g_whh[(size_t)4096 * 1024];        // Wh fp16 hi
__device__ __align__(1024) __half g_whl[(size_t)4096 * 1024];        // Wh fp16 lo
// h image ping-pong: 16 chunks x [128 b x 64 k] fp16, 128B rows, unit u^(b&7)
__device__ __align__(1024) __half g_hf[2][16 * 128 * 64];
__device__ unsigned g_bar;

// ---- PTX helpers (base sm_103 safe) ---------------------------------------
__device__ __forceinline__ u32 sptr(const void* p) {
    u32 a;
    asm("{ .reg .u64 t; cvta.to.shared.u64 t, %1; cvt.u32.u64 %0, t; }" : "=r"(a) : "l"(p));
    return a;
}
__device__ __forceinline__ void mbar_init(u32 m, u32 cnt) {
    asm volatile("mbarrier.init.shared.b64 [%0], %1;" :: "r"(m), "r"(cnt) : "memory");
}
__device__ __forceinline__ void mbar_expect_tx(u32 m, u32 bytes) {
    asm volatile("mbarrier.arrive.expect_tx.shared.b64 _, [%0], %1;" :: "r"(m), "r"(bytes) : "memory");
}
__device__ __forceinline__ void mbar_arrive(u32 m) {
    asm volatile("mbarrier.arrive.shared.b64 _, [%0];" :: "r"(m) : "memory");
}
__device__ __forceinline__ void mwait(u32 m, u32 parity) {
    asm volatile(
        "{\n\t.reg .pred P;\n"
        "W%=:\n\tmbarrier.try_wait.parity.acquire.cta.shared::cta.b64 P, [%0], %1, 0x989680;\n"
        "\t@P bra D%=;\n\tbra W%=;\nD%=:\n\t}" :: "r"(m), "r"(parity) : "memory");
}
__device__ __forceinline__ void bulk_g2s(u32 dst, const void* src, u32 bytes, u32 m) {
    asm volatile(
        "cp.async.bulk.shared::cluster.global.mbarrier::complete_tx::bytes [%0], [%1], %2, [%3];"
        :: "r"(dst), "l"((u64)__cvta_generic_to_global(src)), "r"(bytes), "r"(m) : "memory");
}
__device__ __forceinline__ void f_proxy() { asm volatile("fence.proxy.async;" ::: "memory"); }
__device__ __forceinline__ unsigned ld_acq(const unsigned* p) {
    unsigned v;
    asm volatile("ld.global.acquire.gpu.u32 %0, [%1];" : "=r"(v) : "l"(p));
    return v;
}
__device__ __forceinline__ void ldsm_x4(u32 (&r)[4], u32 addr) {
    asm volatile("ldmatrix.sync.aligned.m8n8.x4.shared.b16 {%0,%1,%2,%3}, [%4];"
                 : "=r"(r[0]), "=r"(r[1]), "=r"(r[2]), "=r"(r[3]) : "r"(addr));
}
__device__ __forceinline__ void mma_fp16(float (&d)[4], const u32 (&a)[4], const u32* b) {
    asm volatile(
        "mma.sync.aligned.m16n8k16.row.col.f32.f16.f16.f32 "
        "{%0,%1,%2,%3}, {%4,%5,%6,%7}, {%8,%9}, {%0,%1,%2,%3};"
        : "+f"(d[0]), "+f"(d[1]), "+f"(d[2]), "+f"(d[3])
        : "r"(a[0]), "r"(a[1]), "r"(a[2]), "r"(a[3]), "r"(b[0]), "r"(b[1]));
}
__device__ __forceinline__ void split_fp16(float v, u16& h, u16& l) {
    __half hb = __float2half_rn(v);
    __half lb = __float2half_rn(v - __half2float(hb));
    h = *(u16*)&hb; l = *(u16*)&lb;
}

// ---- init ------------------------------------------------------------------
__global__ void init_kernel() {
    int i = blockIdx.x * blockDim.x + threadIdx.x;   // 65536
    ((u32*)g_hf[0])[i] = 0u;
    if (i == 0) g_bar = 0u;
}

// ---- conversions to blocked swizzled images --------------------------------
// x A-image: [mt][kc(16)][128 rows x 64 k] fp16, row=128B, unit u -> u^(row&7)
__global__ void conv_x_kernel(const float* __restrict__ x) {
    size_t idx = (size_t)blockIdx.x * 256 + threadIdx.x;   // 16,777,216
    u32 m = (u32)(idx >> 7), ku = (u32)(idx & 127);
    const float4* src = (const float4*)(x + (size_t)m * 1024 + ku * 8);
    float4 a = src[0], b = src[1];
    float v[8] = {a.x, a.y, a.z, a.w, b.x, b.y, b.z, b.w};
    union { u16 s[8]; uint4 q; } F;
#pragma unroll
    for (int i = 0; i < 8; i++) {
        __half hv = __float2half_rn(v[i]);
        F.s[i] = *(u16*)&hv;
    }
    u32 mt = m >> 7, r = m & 127, kc = ku >> 3, uu = ku & 7;
    size_t off = ((size_t)(mt * 16 + kc) << 13) + (r << 6) + ((uu ^ (r & 7)) << 3);
    *(uint4*)(g_xf + off) = F.q;
}
// Wi B-image: [nt(32)][kc(16)][128 n x 64 k] fp16
__global__ void conv_wi_kernel(const float* __restrict__ W0, const float* __restrict__ W1,
                               const float* __restrict__ W2, const float* __restrict__ W3) {
    u32 idx = blockIdx.x * 256 + threadIdx.x;   // 524288
    u32 n = idx & 4095, ku = idx >> 12;
    const float* __restrict__ W = (n < 1024) ? W0 : (n < 2048) ? W1 : (n < 3072) ? W2 : W3;
    u32 col = n & 1023;
    union { u16 s[8]; uint4 q; } F;
#pragma unroll
    for (int i = 0; i < 8; i++) {
        __half hv = __float2half_rn(W[(size_t)(ku * 8 + i) * 1024 + col]);
        F.s[i] = *(u16*)&hv;
    }
    u32 nt = n >> 7, r = n & 127, kc = ku >> 3, uu = ku & 7;
    size_t off = ((size_t)(nt * 16 + kc) << 13) + (r << 6) + ((uu ^ (r & 7)) << 3);
    *(uint4*)(g_wif + off) = F.q;
}
// Wh B-image: [cb(128)][32 rows(j=g*8+(n&7)) x 1024 k] fp16 hi/lo, row=2048B
// off is in ELEMENTS (2B): cb<<15 elems = 65536B slice, j<<10 elems = 2048B row.
__global__ void conv_wh_kernel(const float* __restrict__ W0, const float* __restrict__ W1,
                               const float* __restrict__ W2, const float* __restrict__ W3) {
    u32 idx = blockIdx.x * 256 + threadIdx.x;   // 524288
    u32 n = idx & 1023, ku = (idx >> 10) & 127, g = idx >> 17;
    const float* __restrict__ W = (g == 0) ? W0 : (g == 1) ? W1 : (g == 2) ? W2 : W3;
    union { u16 s[8]; uint4 q; } H, L;
#pragma unroll
    for (int i = 0; i < 8; i++)
        split_fp16(W[(size_t)(ku * 8 + i) * 1024 + n], H.s[i], L.s[i]);
    u32 cb = n >> 3, j = g * 8 + (n & 7);
    size_t off = ((size_t)cb << 15) + (j << 10) + ((ku ^ (j & 7)) << 3);
    *(uint4*)(g_whh + off) = H.q;
    *(uint4*)(g_whl + off) = L.q;
}

// ---- Phase 1: x_proj = x @ Wi + bias. fp16 MMA (R8-proven, unchanged) ------
__global__ void __launch_bounds__(256, 1) xproj_mma(
    const float* __restrict__ b_i, const float* __restrict__ b_f,
    const float* __restrict__ b_g, const float* __restrict__ b_o)
{
    extern __shared__ __align__(1024) char smem[];
    const u32 sb = sptr(smem);
    const int tid = threadIdx.x, lane = tid & 31, w = tid >> 5;
    const int bx = blockIdx.x, by = blockIdx.y;
    const u32 SA = sb + 1024, SBB = sb + 33792;

    if (tid == 0) {
        mbar_init(sb + 0, 1);   mbar_init(sb + 8, 1);     // full
        mbar_init(sb + 16, 256); mbar_init(sb + 24, 256); // empty
    }
    __syncthreads();

    const char* ax = (const char*)g_xf + (size_t)by * 262144;
    const char* bw = (const char*)g_wif + (size_t)bx * 262144;

    auto issue = [&](int c) {
        int buf = c & 1;
        mwait(sb + 16 + buf * 8, ((c >> 1) & 1) ^ 1);
        mbar_expect_tx(sb + buf * 8, 32768);
        bulk_g2s(SA + buf * 16384,  ax + (size_t)c * 16384, 16384, sb + buf * 8);
        bulk_g2s(SBB + buf * 16384, bw + (size_t)c * 16384, 16384, sb + buf * 8);
    };
    if (tid == 0) { issue(0); issue(1); }

    const int wr = w >> 2, wc = w & 3;
    const int arow = (lane & 7) + ((lane >> 3) & 1) * 8;
    const int aub  = lane >> 4;
    const int brow = (lane & 7) + (lane >> 4) * 8;
    const int bub  = (lane >> 3) & 1;

    float acc[4][4][4];
#pragma unroll
    for (int i = 0; i < 4; i++)
#pragma unroll
        for (int j = 0; j < 4; j++)
#pragma unroll
            for (int q = 0; q < 4; q++) acc[i][j][q] = 0.f;

    for (int c = 0; c < 16; c++) {
        int buf = c & 1;
        mwait(sb + buf * 8, (c >> 1) & 1);
        u32 Ab = SA + buf * 16384, Bb = SBB + buf * 16384;
#pragma unroll
        for (int s = 0; s < 4; s++) {
            u32 a4[4][4];
#pragma unroll
            for (int mt = 0; mt < 4; mt++) {
                int r = wr * 64 + mt * 16 + arow;
                u32 off = (u32)(r * 128 + (((s * 2 + aub) ^ (r & 7)) << 4));
                ldsm_x4(a4[mt], Ab + off);
            }
#pragma unroll
            for (int np = 0; np < 2; np++) {
                int n = wc * 32 + np * 16 + brow;
                u32 off = (u32)(n * 128 + (((s * 2 + bub) ^ (n & 7)) << 4));
                u32 b4[4];
                ldsm_x4(b4, Bb + off);
#pragma unroll
                for (int mt = 0; mt < 4; mt++) {
                    mma_fp16(acc[mt][np * 2 + 0], a4[mt], b4 + 0);
                    mma_fp16(acc[mt][np * 2 + 1], a4[mt], b4 + 2);
                }
            }
        }
        mbar_arrive(sb + 16 + buf * 8);
        if (tid == 0 && c < 14) issue(c + 2);
    }

    const int gate = bx >> 3;
    const float* __restrict__ bias =
        (gate == 0) ? b_i : (gate == 1) ? b_f : (gate == 2) ? b_g : b_o;
    const int bcol0 = (bx & 7) * 128 + wc * 32 + (lane & 3) * 2;
    float2 bv[4];
#pragma unroll
    for (int nt = 0; nt < 4; nt++)
        bv[nt] = make_float2(bias[bcol0 + nt * 8], bias[bcol0 + nt * 8 + 1]);

    const int colg = bx * 128 + wc * 32 + (lane & 3) * 2;
#pragma unroll
    for (int mt = 0; mt < 4; mt++) {
#pragma unroll
        for (int h2 = 0; h2 < 2; h2++) {
            int m = by * 128 + wr * 64 + mt * 16 + (lane >> 2) + h2 * 8;
            int bb = m >> 10, t = m & 1023;
            float* __restrict__ xp =
                ((t < 512) ? g_xp0 : g_xp1) + ((size_t)(t & 511) * 128 + bb) * 4096 + colg;
#pragma unroll
            for (int nt = 0; nt < 4; nt++) {
                float2 o = make_float2(acc[mt][nt][h2 * 2 + 0] + bv[nt].x,
                                       acc[mt][nt][h2 * 2 + 1] + bv[nt].y);
                *(float2*)(xp + nt * 8) = o;
            }
        }
    }
}

// ---- Phase 2 (persistent, R8 structure): 128 CTAs x 256 thr ----------------
// h = fp16 single (A), Wh = fp16 hi/lo (B): gates = ah*bh + ah*bl (2 MMAs).
// Halves h L2 broadcast and A traffic; tensor 12288->8192 cyc/step/SM.
__global__ void __launch_bounds__(256, 1) lstm_mma(float* __restrict__ out)
{
    extern __shared__ __align__(1024) char smem[];
    const u32 sb = sptr(smem);
    const int tid = threadIdx.x, lane = tid & 31, w = tid >> 5;
    const int cb = blockIdx.x;
    const u32 SBH = sb + 1024, SBL = sb + 66560, SA = sb + 132096;  // 2 x 16KB A bufs

    if (tid == 0) {
        mbar_init(sb + 0, 1);   mbar_init(sb + 8, 1);     // full
        mbar_init(sb + 16, 256); mbar_init(sb + 24, 256); // empty
        mbar_init(sb + 32, 1);                            // Wh
        mbar_expect_tx(sb + 32, 131072);
        bulk_g2s(SBH, (const char*)g_whh + (size_t)cb * 65536, 65536, sb + 32);
        bulk_g2s(SBL, (const char*)g_whl + (size_t)cb * 65536, 65536, sb + 32);
    }
    __syncthreads();
    mwait(sb + 32, 0);

    const int arow = (lane & 7) + ((lane >> 3) & 1) * 8;
    const int aub  = lane >> 4;
    const int brow = (lane & 7) + (lane >> 4) * 8;
    const int bub  = (lane >> 3) & 1;
    const int r0 = w * 16 + (lane >> 2), p = lane & 3;
    const u32 aoff_base = (u32)((w * 16 + arow) * 128);
    const int ar7 = (w * 16 + arow) & 7;

    auto issue = [&](int t, int c) {
        int buf = c & 1;
        mwait(sb + 16 + buf * 8, ((c >> 1) & 1) ^ 1);
        mbar_expect_tx(sb + buf * 8, 16384);
        bulk_g2s(SA + buf * 16384,
                 (const char*)g_hf[t & 1] + (size_t)c * 16384, 16384, sb + buf * 8);
    };

    float cst[2][2] = {{0.f, 0.f}, {0.f, 0.f}};

    for (int t = 0; t < TT; t++) {
        if (tid == 0) { f_proxy(); issue(t, 0); issue(t, 1); }

        // prefetch xp gate values for this thread's 4 outputs (hide L2 latency)
        const float* xpb = ((t < 512) ? g_xp0 : g_xp1) + (size_t)(t & 511) * 524288;
        float2 xg[2][4];
#pragma unroll
        for (int half = 0; half < 2; half++) {
            const float* xr = xpb + (size_t)(r0 + half * 8) * 4096 + cb * 8 + p * 2;
            xg[half][0] = *(const float2*)(xr);
            xg[half][1] = *(const float2*)(xr + 1024);
            xg[half][2] = *(const float2*)(xr + 2048);
            xg[half][3] = *(const float2*)(xr + 3072);
        }

        float acc[4][4];
#pragma unroll
        for (int i = 0; i < 4; i++)
#pragma unroll
            for (int q = 0; q < 4; q++) acc[i][q] = 0.f;

        for (int c = 0; c < 16; c++) {
            int buf = c & 1;
            mwait(sb + buf * 8, (c >> 1) & 1);
            u32 Ab = SA + buf * 16384;
#pragma unroll
            for (int s = 0; s < 4; s++) {
                u32 ah[4];
                u32 aoff = aoff_base + (((s * 2 + aub) ^ ar7) << 4);
                ldsm_x4(ah, Ab + aoff);
                int kk2 = (c * 4 + s) * 2 + bub;
#pragma unroll
                for (int np = 0; np < 2; np++) {
                    int j = np * 16 + brow;
                    u32 boff = (u32)(j * 2048 + ((kk2 ^ (j & 7)) << 4));
                    u32 bh[4], bl[4];
                    ldsm_x4(bh, SBH + boff);
                    ldsm_x4(bl, SBL + boff);
                    mma_fp16(acc[np * 2 + 0], ah, bh + 0);
                    mma_fp16(acc[np * 2 + 0], ah, bl + 0);
                    mma_fp16(acc[np * 2 + 1], ah, bh + 2);
                    mma_fp16(acc[np * 2 + 1], ah, bl + 2);
                }
            }
            mbar_arrive(sb + 16 + buf * 8);
            if (tid == 0 && c < 14) issue(t, c + 2);
        }

        // epilogue: acc[0..3] = gates i,f,g,o at cols jj=2p,2p+1; rows r0, r0+8
        float hv[2][2];
#pragma unroll
        for (int half = 0; half < 2; half++) {
            int b = r0 + half * 8;
#pragma unroll
            for (int q = 0; q < 2; q++) {
                float iv = acc[0][half * 2 + q] + (q ? xg[half][0].y : xg[half][0].x);
                float fv = acc[1][half * 2 + q] + (q ? xg[half][1].y : xg[half][1].x);
                float gv = acc[2][half * 2 + q] + (q ? xg[half][2].y : xg[half][2].x);
                float ov = acc[3][half * 2 + q] + (q ? xg[half][3].y : xg[half][3].x);
                float si = 1.f / (1.f + expf(-iv));
                float sf = 1.f / (1.f + expf(-fv));
                float tg = tanhf(gv);
                float so = 1.f / (1.f + expf(-ov));
                cst[half][q] = sf * cst[half][q] + si * tg;
                hv[half][q] = so * tanhf(cst[half][q]);
            }
            __half f0 = __float2half_rn(hv[half][0]);
            __half f1 = __float2half_rn(hv[half][1]);
            u32 hw = (u32)(*(u16*)&f0) | ((u32)(*(u16*)&f1) << 16);
            u32 off = (u32)(cb >> 3) * 16384 + (u32)b * 128
                    + (u32)(((cb & 7) ^ (b & 7)) << 4) + (u32)p * 4;
            *(u32*)((char*)g_hf[(t + 1) & 1] + off) = hw;
        }

        if (t == TT - 1) {
#pragma unroll
            for (int half = 0; half < 2; half++) {
                int b = r0 + half * 8;
                float* o1 = out + (size_t)b * 1024 + cb * 8 + p * 2;
                o1[0] = hv[half][0]; o1[1] = hv[half][1];
                float* o2 = o1 + 131072;
                o2[0] = cst[half][0]; o2[1] = cst[half][1];
            }
        }

        if (t < TT - 1) {   // global barrier (R8-proven)
            __syncthreads();
            if (tid == 0) {
                __threadfence();
                atomicAdd(&g_bar, 1u);
                unsigned tgt = 128u * (unsigned)(t + 1);
                while (ld_acq(&g_bar) < tgt) __nanosleep(64);
            }
            __syncthreads();
        }
    }
}

// ---------------------------------------------------------------------------
extern "C" void kernel_launch(void* const* d_in, const int* in_sizes, int n_in,
                              void* d_out, int out_size)
{
    const float* x   = (const float*)d_in[0];
    const float* Wii = (const float*)d_in[1];
    const float* Wif = (const float*)d_in[2];
    const float* Wig = (const float*)d_in[3];
    const float* Wio = (const float*)d_in[4];
    const float* Whi = (const float*)d_in[5];
    const float* Whf = (const float*)d_in[6];
    const float* Whg = (const float*)d_in[7];
    const float* Who = (const float*)d_in[8];
    const float* b_i = (const float*)d_in[9];
    const float* b_f = (const float*)d_in[10];
    const float* b_g = (const float*)d_in[11];
    const float* b_o = (const float*)d_in[12];
    float* out = (float*)d_out;

    cudaFuncSetAttribute(xproj_mma, cudaFuncAttributeMaxDynamicSharedMemorySize, 66560);
    cudaFuncSetAttribute(lstm_mma,  cudaFuncAttributeMaxDynamicSharedMemorySize, 164864);

    init_kernel<<<256, 256>>>();
    conv_x_kernel<<<65536, 256>>>(x);
    conv_wi_kernel<<<2048, 256>>>(Wii, Wif, Wig, Wio);
    conv_wh_kernel<<<2048, 256>>>(Whi, Whf, Whg, Who);

    dim3 g1(32, 1024);
    xproj_mma<<<g1, 256, 66560>>>(b_i, b_f, b_g, b_o);
    lstm_mma<<<128, 256, 164864>>>(out);
}

// round 15
// speedup vs baseline: 1.8086x; 1.1177x over previous
#include <cuda_runtime.h>
#include <cuda_bf16.h>
#include <cuda_fp16.h>

typedef unsigned int u32;
typedef unsigned long long u64;
typedef unsigned short u16;

#define TT 1024

// ---- device scratch --------------------------------------------------------
__device__ __align__(1024) float g_xp0[(size_t)512 * 128 * 4096];
__device__ __align__(1024) float g_xp1[(size_t)512 * 128 * 4096];
__device__ __align__(1024) __half g_xf[(size_t)128 * 1024 * 1024];   // x fp16 A-image
__device__ __align__(1024) __half g_wif[(size_t)4096 * 1024];        // Wi fp16 B-image
__device__ __align__(1024) __half g_whf[(size_t)4096 * 1024];        // Wh fp16 B-image
// h image ping-pong: 16 chunks x [128 b x 64 k] fp16, 128B rows, unit u^(b&7)
__device__ __align__(1024) __half g_hf[2][16 * 128 * 64];
__device__ unsigned g_bar;

// ---- PTX helpers (base sm_103 safe) ---------------------------------------
__device__ __forceinline__ u32 sptr(const void* p) {
    u32 a;
    asm("{ .reg .u64 t; cvta.to.shared.u64 t, %1; cvt.u32.u64 %0, t; }" : "=r"(a) : "l"(p));
    return a;
}
__device__ __forceinline__ void mbar_init(u32 m, u32 cnt) {
    asm volatile("mbarrier.init.shared.b64 [%0], %1;" :: "r"(m), "r"(cnt) : "memory");
}
__device__ __forceinline__ void mbar_expect_tx(u32 m, u32 bytes) {
    asm volatile("mbarrier.arrive.expect_tx.shared.b64 _, [%0], %1;" :: "r"(m), "r"(bytes) : "memory");
}
__device__ __forceinline__ void mbar_arrive(u32 m) {
    asm volatile("mbarrier.arrive.shared.b64 _, [%0];" :: "r"(m) : "memory");
}
__device__ __forceinline__ void mwait(u32 m, u32 parity) {
    asm volatile(
        "{\n\t.reg .pred P;\n"
        "W%=:\n\tmbarrier.try_wait.parity.acquire.cta.shared::cta.b64 P, [%0], %1, 0x989680;\n"
        "\t@P bra D%=;\n\tbra W%=;\nD%=:\n\t}" :: "r"(m), "r"(parity) : "memory");
}
__device__ __forceinline__ void bulk_g2s(u32 dst, const void* src, u32 bytes, u32 m) {
    asm volatile(
        "cp.async.bulk.shared::cluster.global.mbarrier::complete_tx::bytes [%0], [%1], %2, [%3];"
        :: "r"(dst), "l"((u64)__cvta_generic_to_global(src)), "r"(bytes), "r"(m) : "memory");
}
__device__ __forceinline__ void f_proxy() { asm volatile("fence.proxy.async;" ::: "memory"); }
__device__ __forceinline__ unsigned ld_acq(const unsigned* p) {
    unsigned v;
    asm volatile("ld.global.acquire.gpu.u32 %0, [%1];" : "=r"(v) : "l"(p));
    return v;
}
__device__ __forceinline__ void ldsm_x4(u32 (&r)[4], u32 addr) {
    asm volatile("ldmatrix.sync.aligned.m8n8.x4.shared.b16 {%0,%1,%2,%3}, [%4];"
                 : "=r"(r[0]), "=r"(r[1]), "=r"(r[2]), "=r"(r[3]) : "r"(addr));
}
__device__ __forceinline__ void mma_fp16(float (&d)[4], const u32 (&a)[4], const u32* b) {
    asm volatile(
        "mma.sync.aligned.m16n8k16.row.col.f32.f16.f16.f32 "
        "{%0,%1,%2,%3}, {%4,%5,%6,%7}, {%8,%9}, {%0,%1,%2,%3};"
        : "+f"(d[0]), "+f"(d[1]), "+f"(d[2]), "+f"(d[3])
        : "r"(a[0]), "r"(a[1]), "r"(a[2]), "r"(a[3]), "r"(b[0]), "r"(b[1]));
}

// ---- init ------------------------------------------------------------------
__global__ void init_kernel() {
    int i = blockIdx.x * blockDim.x + threadIdx.x;   // 65536
    ((u32*)g_hf[0])[i] = 0u;
    if (i == 0) g_bar = 0u;
}

// ---- conversions to blocked swizzled images --------------------------------
// x A-image: [mt][kc(16)][128 rows x 64 k] fp16, row=128B, unit u -> u^(row&7)
__global__ void conv_x_kernel(const float* __restrict__ x) {
    size_t idx = (size_t)blockIdx.x * 256 + threadIdx.x;   // 16,777,216
    u32 m = (u32)(idx >> 7), ku = (u32)(idx & 127);
    const float4* src = (const float4*)(x + (size_t)m * 1024 + ku * 8);
    float4 a = src[0], b = src[1];
    float v[8] = {a.x, a.y, a.z, a.w, b.x, b.y, b.z, b.w};
    union { u16 s[8]; uint4 q; } F;
#pragma unroll
    for (int i = 0; i < 8; i++) {
        __half hv = __float2half_rn(v[i]);
        F.s[i] = *(u16*)&hv;
    }
    u32 mt = m >> 7, r = m & 127, kc = ku >> 3, uu = ku & 7;
    size_t off = ((size_t)(mt * 16 + kc) << 13) + (r << 6) + ((uu ^ (r & 7)) << 3);
    *(uint4*)(g_xf + off) = F.q;
}
// Wi B-image: [nt(32)][kc(16)][128 n x 64 k] fp16
__global__ void conv_wi_kernel(const float* __restrict__ W0, const float* __restrict__ W1,
                               const float* __restrict__ W2, const float* __restrict__ W3) {
    u32 idx = blockIdx.x * 256 + threadIdx.x;   // 524288
    u32 n = idx & 4095, ku = idx >> 12;
    const float* __restrict__ W = (n < 1024) ? W0 : (n < 2048) ? W1 : (n < 3072) ? W2 : W3;
    u32 col = n & 1023;
    union { u16 s[8]; uint4 q; } F;
#pragma unroll
    for (int i = 0; i < 8; i++) {
        __half hv = __float2half_rn(W[(size_t)(ku * 8 + i) * 1024 + col]);
        F.s[i] = *(u16*)&hv;
    }
    u32 nt = n >> 7, r = n & 127, kc = ku >> 3, uu = ku & 7;
    size_t off = ((size_t)(nt * 16 + kc) << 13) + (r << 6) + ((uu ^ (r & 7)) << 3);
    *(uint4*)(g_wif + off) = F.q;
}
// Wh B-image: [cb(128)][32 rows(j=g*8+(n&7)) x 1024 k] fp16 single, row=2048B
// off in ELEMENTS (2B): cb<<15 elems = 64KB slice, j<<10 elems = 2048B row.
__global__ void conv_wh_kernel(const float* __restrict__ W0, const float* __restrict__ W1,
                               const float* __restrict__ W2, const float* __restrict__ W3) {
    u32 idx = blockIdx.x * 256 + threadIdx.x;   // 524288
    u32 n = idx & 1023, ku = (idx >> 10) & 127, g = idx >> 17;
    const float* __restrict__ W = (g == 0) ? W0 : (g == 1) ? W1 : (g == 2) ? W2 : W3;
    union { u16 s[8]; uint4 q; } F;
#pragma unroll
    for (int i = 0; i < 8; i++) {
        __half hv = __float2half_rn(W[(size_t)(ku * 8 + i) * 1024 + n]);
        F.s[i] = *(u16*)&hv;
    }
    u32 cb = n >> 3, j = g * 8 + (n & 7);
    size_t off = ((size_t)cb << 15) + (j << 10) + ((ku ^ (j & 7)) << 3);
    *(uint4*)(g_whf + off) = F.q;
}

// ---- Phase 1: x_proj = x @ Wi + bias. fp16 MMA (R8-proven, unchanged) ------
__global__ void __launch_bounds__(256, 1) xproj_mma(
    const float* __restrict__ b_i, const float* __restrict__ b_f,
    const float* __restrict__ b_g, const float* __restrict__ b_o)
{
    extern __shared__ __align__(1024) char smem[];
    const u32 sb = sptr(smem);
    const int tid = threadIdx.x, lane = tid & 31, w = tid >> 5;
    const int bx = blockIdx.x, by = blockIdx.y;
    const u32 SA = sb + 1024, SBB = sb + 33792;

    if (tid == 0) {
        mbar_init(sb + 0, 1);   mbar_init(sb + 8, 1);     // full
        mbar_init(sb + 16, 256); mbar_init(sb + 24, 256); // empty
    }
    __syncthreads();

    const char* ax = (const char*)g_xf + (size_t)by * 262144;
    const char* bw = (const char*)g_wif + (size_t)bx * 262144;

    auto issue = [&](int c) {
        int buf = c & 1;
        mwait(sb + 16 + buf * 8, ((c >> 1) & 1) ^ 1);
        mbar_expect_tx(sb + buf * 8, 32768);
        bulk_g2s(SA + buf * 16384,  ax + (size_t)c * 16384, 16384, sb + buf * 8);
        bulk_g2s(SBB + buf * 16384, bw + (size_t)c * 16384, 16384, sb + buf * 8);
    };
    if (tid == 0) { issue(0); issue(1); }

    const int wr = w >> 2, wc = w & 3;
    const int arow = (lane & 7) + ((lane >> 3) & 1) * 8;
    const int aub  = lane >> 4;
    const int brow = (lane & 7) + (lane >> 4) * 8;
    const int bub  = (lane >> 3) & 1;

    float acc[4][4][4];
#pragma unroll
    for (int i = 0; i < 4; i++)
#pragma unroll
        for (int j = 0; j < 4; j++)
#pragma unroll
            for (int q = 0; q < 4; q++) acc[i][j][q] = 0.f;

    for (int c = 0; c < 16; c++) {
        int buf = c & 1;
        mwait(sb + buf * 8, (c >> 1) & 1);
        u32 Ab = SA + buf * 16384, Bb = SBB + buf * 16384;
#pragma unroll
        for (int s = 0; s < 4; s++) {
            u32 a4[4][4];
#pragma unroll
            for (int mt = 0; mt < 4; mt++) {
                int r = wr * 64 + mt * 16 + arow;
                u32 off = (u32)(r * 128 + (((s * 2 + aub) ^ (r & 7)) << 4));
                ldsm_x4(a4[mt], Ab + off);
            }
#pragma unroll
            for (int np = 0; np < 2; np++) {
                int n = wc * 32 + np * 16 + brow;
                u32 off = (u32)(n * 128 + (((s * 2 + bub) ^ (n & 7)) << 4));
                u32 b4[4];
                ldsm_x4(b4, Bb + off);
#pragma unroll
                for (int mt = 0; mt < 4; mt++) {
                    mma_fp16(acc[mt][np * 2 + 0], a4[mt], b4 + 0);
                    mma_fp16(acc[mt][np * 2 + 1], a4[mt], b4 + 2);
                }
            }
        }
        mbar_arrive(sb + 16 + buf * 8);
        if (tid == 0 && c < 14) issue(c + 2);
    }

    const int gate = bx >> 3;
    const float* __restrict__ bias =
        (gate == 0) ? b_i : (gate == 1) ? b_f : (gate == 2) ? b_g : b_o;
    const int bcol0 = (bx & 7) * 128 + wc * 32 + (lane & 3) * 2;
    float2 bv[4];
#pragma unroll
    for (int nt = 0; nt < 4; nt++)
        bv[nt] = make_float2(bias[bcol0 + nt * 8], bias[bcol0 + nt * 8 + 1]);

    const int colg = bx * 128 + wc * 32 + (lane & 3) * 2;
#pragma unroll
    for (int mt = 0; mt < 4; mt++) {
#pragma unroll
        for (int h2 = 0; h2 < 2; h2++) {
            int m = by * 128 + wr * 64 + mt * 16 + (lane >> 2) + h2 * 8;
            int bb = m >> 10, t = m & 1023;
            float* __restrict__ xp =
                ((t < 512) ? g_xp0 : g_xp1) + ((size_t)(t & 511) * 128 + bb) * 4096 + colg;
#pragma unroll
            for (int nt = 0; nt < 4; nt++) {
                float2 o = make_float2(acc[mt][nt][h2 * 2 + 0] + bv[nt].x,
                                       acc[mt][nt][h2 * 2 + 1] + bv[nt].y);
                *(float2*)(xp + nt * 8) = o;
            }
        }
    }
}

// ---- Phase 2 (persistent, R8 structure): 128 CTAs x 256 thr ----------------
// h fp16 x Wh fp16 single: 1 MMA per (s,np). Tensor 4096 cyc/step/SM,
// ldsm 6144 wf, h broadcast 32 MB/step.
__global__ void __launch_bounds__(256, 1) lstm_mma(float* __restrict__ out)
{
    extern __shared__ __align__(1024) char smem[];
    const u32 sb = sptr(smem);
    const int tid = threadIdx.x, lane = tid & 31, w = tid >> 5;
    const int cb = blockIdx.x;
    const u32 SBH = sb + 1024, SA = sb + 66560;   // Wh 64KB; 2 x 16KB A bufs

    if (tid == 0) {
        mbar_init(sb + 0, 1);   mbar_init(sb + 8, 1);     // full
        mbar_init(sb + 16, 256); mbar_init(sb + 24, 256); // empty
        mbar_init(sb + 32, 1);                            // Wh
        mbar_expect_tx(sb + 32, 65536);
        bulk_g2s(SBH, (const char*)g_whf + (size_t)cb * 65536, 65536, sb + 32);
    }
    __syncthreads();
    mwait(sb + 32, 0);

    const int arow = (lane & 7) + ((lane >> 3) & 1) * 8;
    const int aub  = lane >> 4;
    const int brow = (lane & 7) + (lane >> 4) * 8;
    const int bub  = (lane >> 3) & 1;
    const int r0 = w * 16 + (lane >> 2), p = lane & 3;
    const u32 aoff_base = (u32)((w * 16 + arow) * 128);
    const int ar7 = (w * 16 + arow) & 7;

    auto issue = [&](int t, int c) {
        int buf = c & 1;
        mwait(sb + 16 + buf * 8, ((c >> 1) & 1) ^ 1);
        mbar_expect_tx(sb + buf * 8, 16384);
        bulk_g2s(SA + buf * 16384,
                 (const char*)g_hf[t & 1] + (size_t)c * 16384, 16384, sb + buf * 8);
    };

    float cst[2][2] = {{0.f, 0.f}, {0.f, 0.f}};

    for (int t = 0; t < TT; t++) {
        if (tid == 0) { f_proxy(); issue(t, 0); issue(t, 1); }

        // prefetch xp gate values for this thread's 4 outputs (hide L2 latency)
        const float* xpb = ((t < 512) ? g_xp0 : g_xp1) + (size_t)(t & 511) * 524288;
        float2 xg[2][4];
#pragma unroll
        for (int half = 0; half < 2; half++) {
            const float* xr = xpb + (size_t)(r0 + half * 8) * 4096 + cb * 8 + p * 2;
            xg[half][0] = *(const float2*)(xr);
            xg[half][1] = *(const float2*)(xr + 1024);
            xg[half][2] = *(const float2*)(xr + 2048);
            xg[half][3] = *(const float2*)(xr + 3072);
        }

        float acc[4][4];
#pragma unroll
        for (int i = 0; i < 4; i++)
#pragma unroll
            for (int q = 0; q < 4; q++) acc[i][q] = 0.f;

        for (int c = 0; c < 16; c++) {
            int buf = c & 1;
            mwait(sb + buf * 8, (c >> 1) & 1);
            u32 Ab = SA + buf * 16384;
#pragma unroll
            for (int s = 0; s < 4; s++) {
                u32 ah[4];
                u32 aoff = aoff_base + (((s * 2 + aub) ^ ar7) << 4);
                ldsm_x4(ah, Ab + aoff);
                int kk2 = (c * 4 + s) * 2 + bub;
#pragma unroll
                for (int np = 0; np < 2; np++) {
                    int j = np * 16 + brow;
                    u32 boff = (u32)(j * 2048 + ((kk2 ^ (j & 7)) << 4));
                    u32 bh[4];
                    ldsm_x4(bh, SBH + boff);
                    mma_fp16(acc[np * 2 + 0], ah, bh + 0);
                    mma_fp16(acc[np * 2 + 1], ah, bh + 2);
                }
            }
            mbar_arrive(sb + 16 + buf * 8);
            if (tid == 0 && c < 14) issue(t, c + 2);
        }

        // epilogue: acc[0..3] = gates i,f,g,o at cols jj=2p,2p+1; rows r0, r0+8
        float hv[2][2];
#pragma unroll
        for (int half = 0; half < 2; half++) {
            int b = r0 + half * 8;
#pragma unroll
            for (int q = 0; q < 2; q++) {
                float iv = acc[0][half * 2 + q] + (q ? xg[half][0].y : xg[half][0].x);
                float fv = acc[1][half * 2 + q] + (q ? xg[half][1].y : xg[half][1].x);
                float gv = acc[2][half * 2 + q] + (q ? xg[half][2].y : xg[half][2].x);
                float ov = acc[3][half * 2 + q] + (q ? xg[half][3].y : xg[half][3].x);
                float si = 1.f / (1.f + expf(-iv));
                float sf = 1.f / (1.f + expf(-fv));
                float tg = tanhf(gv);
                float so = 1.f / (1.f + expf(-ov));
                cst[half][q] = sf * cst[half][q] + si * tg;
                hv[half][q] = so * tanhf(cst[half][q]);
            }
            __half f0 = __float2half_rn(hv[half][0]);
            __half f1 = __float2half_rn(hv[half][1]);
            u32 hw = (u32)(*(u16*)&f0) | ((u32)(*(u16*)&f1) << 16);
            u32 off = (u32)(cb >> 3) * 16384 + (u32)b * 128
                    + (u32)(((cb & 7) ^ (b & 7)) << 4) + (u32)p * 4;
            *(u32*)((char*)g_hf[(t + 1) & 1] + off) = hw;
        }

        if (t == TT - 1) {
#pragma unroll
            for (int half = 0; half < 2; half++) {
                int b = r0 + half * 8;
                float* o1 = out + (size_t)b * 1024 + cb * 8 + p * 2;
                o1[0] = hv[half][0]; o1[1] = hv[half][1];
                float* o2 = o1 + 131072;
                o2[0] = cst[half][0]; o2[1] = cst[half][1];
            }
        }

        if (t < TT - 1) {   // global barrier (R8-proven)
            __syncthreads();
            if (tid == 0) {
                __threadfence();
                atomicAdd(&g_bar, 1u);
                unsigned tgt = 128u * (unsigned)(t + 1);
                while (ld_acq(&g_bar) < tgt) __nanosleep(64);
            }
            __syncthreads();
        }
    }
}

// ---------------------------------------------------------------------------
extern "C" void kernel_launch(void* const* d_in, const int* in_sizes, int n_in,
                              void* d_out, int out_size)
{
    const float* x   = (const float*)d_in[0];
    const float* Wii = (const float*)d_in[1];
    const float* Wif = (const float*)d_in[2];
    const float* Wig = (const float*)d_in[3];
    const float* Wio = (const float*)d_in[4];
    const float* Whi = (const float*)d_in[5];
    const float* Whf = (const float*)d_in[6];
    const float* Whg = (const float*)d_in[7];
    const float* Who = (const float*)d_in[8];
    const float* b_i = (const float*)d_in[9];
    const float* b_f = (const float*)d_in[10];
    const float* b_g = (const float*)d_in[11];
    const float* b_o = (const float*)d_in[12];
    float* out = (float*)d_out;

    cudaFuncSetAttribute(xproj_mma, cudaFuncAttributeMaxDynamicSharedMemorySize, 66560);
    cudaFuncSetAttribute(lstm_mma,  cudaFuncAttributeMaxDynamicSharedMemorySize, 99328);

    init_kernel<<<256, 256>>>();
    conv_x_kernel<<<65536, 256>>>(x);
    conv_wi_kernel<<<2048, 256>>>(Wii, Wif, Wig, Wio);
    conv_wh_kernel<<<2048, 256>>>(Whi, Whf, Whg, Who);

    dim3 g1(32, 1024);
    xproj_mma<<<g1, 256, 66560>>>(b_i, b_f, b_g, b_o);
    lstm_mma<<<128, 256, 99328>>>(out);
}

// round 16
// speedup vs baseline: 1.8094x; 1.0004x over previous
#include <cuda_runtime.h>
#include <cuda_bf16.h>
#include <cuda_fp16.h>

typedef unsigned int u32;
typedef unsigned long long u64;
typedef unsigned short u16;

#define TT 1024

// ---- device scratch --------------------------------------------------------
__device__ __align__(1024) float g_xp0[(size_t)512 * 128 * 4096];
__device__ __align__(1024) float g_xp1[(size_t)512 * 128 * 4096];
__device__ __align__(1024) __half g_xf[(size_t)128 * 1024 * 1024];   // x fp16 A-image
__device__ __align__(1024) __half g_wif[(size_t)4096 * 1024];        // Wi fp16 B-image
__device__ __align__(1024) __half g_whf[(size_t)4096 * 1024];        // Wh fp16 B-image
// h image ping-pong: 16 chunks x [128 b x 64 k] fp16, 128B rows, unit u^(b&7)
__device__ __align__(1024) __half g_hf[2][16 * 128 * 64];
__device__ unsigned g_bar;
__device__ unsigned g_early;   // producers of h chunks 0,1 (CTAs 0..15)

// ---- PTX helpers (base sm_103 safe) ---------------------------------------
__device__ __forceinline__ u32 sptr(const void* p) {
    u32 a;
    asm("{ .reg .u64 t; cvta.to.shared.u64 t, %1; cvt.u32.u64 %0, t; }" : "=r"(a) : "l"(p));
    return a;
}
__device__ __forceinline__ void mbar_init(u32 m, u32 cnt) {
    asm volatile("mbarrier.init.shared.b64 [%0], %1;" :: "r"(m), "r"(cnt) : "memory");
}
__device__ __forceinline__ void mbar_expect_tx(u32 m, u32 bytes) {
    asm volatile("mbarrier.arrive.expect_tx.shared.b64 _, [%0], %1;" :: "r"(m), "r"(bytes) : "memory");
}
__device__ __forceinline__ void mbar_arrive(u32 m) {
    asm volatile("mbarrier.arrive.shared.b64 _, [%0];" :: "r"(m) : "memory");
}
__device__ __forceinline__ void mwait(u32 m, u32 parity) {
    asm volatile(
        "{\n\t.reg .pred P;\n"
        "W%=:\n\tmbarrier.try_wait.parity.acquire.cta.shared::cta.b64 P, [%0], %1, 0x989680;\n"
        "\t@P bra D%=;\n\tbra W%=;\nD%=:\n\t}" :: "r"(m), "r"(parity) : "memory");
}
__device__ __forceinline__ void bulk_g2s(u32 dst, const void* src, u32 bytes, u32 m) {
    asm volatile(
        "cp.async.bulk.shared::cluster.global.mbarrier::complete_tx::bytes [%0], [%1], %2, [%3];"
        :: "r"(dst), "l"((u64)__cvta_generic_to_global(src)), "r"(bytes), "r"(m) : "memory");
}
__device__ __forceinline__ void f_proxy() { asm volatile("fence.proxy.async;" ::: "memory"); }
__device__ __forceinline__ unsigned ld_acq(const unsigned* p) {
    unsigned v;
    asm volatile("ld.global.acquire.gpu.u32 %0, [%1];" : "=r"(v) : "l"(p));
    return v;
}
__device__ __forceinline__ void ldsm_x4(u32 (&r)[4], u32 addr) {
    asm volatile("ldmatrix.sync.aligned.m8n8.x4.shared.b16 {%0,%1,%2,%3}, [%4];"
                 : "=r"(r[0]), "=r"(r[1]), "=r"(r[2]), "=r"(r[3]) : "r"(addr));
}
__device__ __forceinline__ void mma_fp16(float (&d)[4], const u32 (&a)[4], const u32* b) {
    asm volatile(
        "mma.sync.aligned.m16n8k16.row.col.f32.f16.f16.f32 "
        "{%0,%1,%2,%3}, {%4,%5,%6,%7}, {%8,%9}, {%0,%1,%2,%3};"
        : "+f"(d[0]), "+f"(d[1]), "+f"(d[2]), "+f"(d[3])
        : "r"(a[0]), "r"(a[1]), "r"(a[2]), "r"(a[3]), "r"(b[0]), "r"(b[1]));
}

// ---- init ------------------------------------------------------------------
__global__ void init_kernel() {
    int i = blockIdx.x * blockDim.x + threadIdx.x;   // 65536
    ((u32*)g_hf[0])[i] = 0u;
    if (i == 0) { g_bar = 0u; g_early = 0u; }
}

// ---- conversions to blocked swizzled images --------------------------------
// x A-image: [mt][kc(16)][128 rows x 64 k] fp16, row=128B, unit u -> u^(row&7)
__global__ void conv_x_kernel(const float* __restrict__ x) {
    size_t idx = (size_t)blockIdx.x * 256 + threadIdx.x;   // 16,777,216
    u32 m = (u32)(idx >> 7), ku = (u32)(idx & 127);
    const float4* src = (const float4*)(x + (size_t)m * 1024 + ku * 8);
    float4 a = src[0], b = src[1];
    float v[8] = {a.x, a.y, a.z, a.w, b.x, b.y, b.z, b.w};
    union { u16 s[8]; uint4 q; } F;
#pragma unroll
    for (int i = 0; i < 8; i++) {
        __half hv = __float2half_rn(v[i]);
        F.s[i] = *(u16*)&hv;
    }
    u32 mt = m >> 7, r = m & 127, kc = ku >> 3, uu = ku & 7;
    size_t off = ((size_t)(mt * 16 + kc) << 13) + (r << 6) + ((uu ^ (r & 7)) << 3);
    *(uint4*)(g_xf + off) = F.q;
}
// Wi B-image: [nt(32)][kc(16)][128 n x 64 k] fp16
__global__ void conv_wi_kernel(const float* __restrict__ W0, const float* __restrict__ W1,
                               const float* __restrict__ W2, const float* __restrict__ W3) {
    u32 idx = blockIdx.x * 256 + threadIdx.x;   // 524288
    u32 n = idx & 4095, ku = idx >> 12;
    const float* __restrict__ W = (n < 1024) ? W0 : (n < 2048) ? W1 : (n < 3072) ? W2 : W3;
    u32 col = n & 1023;
    union { u16 s[8]; uint4 q; } F;
#pragma unroll
    for (int i = 0; i < 8; i++) {
        __half hv = __float2half_rn(W[(size_t)(ku * 8 + i) * 1024 + col]);
        F.s[i] = *(u16*)&hv;
    }
    u32 nt = n >> 7, r = n & 127, kc = ku >> 3, uu = ku & 7;
    size_t off = ((size_t)(nt * 16 + kc) << 13) + (r << 6) + ((uu ^ (r & 7)) << 3);
    *(uint4*)(g_wif + off) = F.q;
}
// Wh B-image: [cb(128)][32 rows(j=g*8+(n&7)) x 1024 k] fp16 single, row=2048B
__global__ void conv_wh_kernel(const float* __restrict__ W0, const float* __restrict__ W1,
                               const float* __restrict__ W2, const float* __restrict__ W3) {
    u32 idx = blockIdx.x * 256 + threadIdx.x;   // 524288
    u32 n = idx & 1023, ku = (idx >> 10) & 127, g = idx >> 17;
    const float* __restrict__ W = (g == 0) ? W0 : (g == 1) ? W1 : (g == 2) ? W2 : W3;
    union { u16 s[8]; uint4 q; } F;
#pragma unroll
    for (int i = 0; i < 8; i++) {
        __half hv = __float2half_rn(W[(size_t)(ku * 8 + i) * 1024 + n]);
        F.s[i] = *(u16*)&hv;
    }
    u32 cb = n >> 3, j = g * 8 + (n & 7);
    size_t off = ((size_t)cb << 15) + (j << 10) + ((ku ^ (j & 7)) << 3);
    *(uint4*)(g_whf + off) = F.q;
}

// ---- Phase 1: x_proj = x @ Wi + bias. fp16 MMA (unchanged) -----------------
__global__ void __launch_bounds__(256, 1) xproj_mma(
    const float* __restrict__ b_i, const float* __restrict__ b_f,
    const float* __restrict__ b_g, const float* __restrict__ b_o)
{
    extern __shared__ __align__(1024) char smem[];
    const u32 sb = sptr(smem);
    const int tid = threadIdx.x, lane = tid & 31, w = tid >> 5;
    const int bx = blockIdx.x, by = blockIdx.y;
    const u32 SA = sb + 1024, SBB = sb + 33792;

    if (tid == 0) {
        mbar_init(sb + 0, 1);   mbar_init(sb + 8, 1);     // full
        mbar_init(sb + 16, 256); mbar_init(sb + 24, 256); // empty
    }
    __syncthreads();

    const char* ax = (const char*)g_xf + (size_t)by * 262144;
    const char* bw = (const char*)g_wif + (size_t)bx * 262144;

    auto issue = [&](int c) {
        int buf = c & 1;
        mwait(sb + 16 + buf * 8, ((c >> 1) & 1) ^ 1);
        mbar_expect_tx(sb + buf * 8, 32768);
        bulk_g2s(SA + buf * 16384,  ax + (size_t)c * 16384, 16384, sb + buf * 8);
        bulk_g2s(SBB + buf * 16384, bw + (size_t)c * 16384, 16384, sb + buf * 8);
    };
    if (tid == 0) { issue(0); issue(1); }

    const int wr = w >> 2, wc = w & 3;
    const int arow = (lane & 7) + ((lane >> 3) & 1) * 8;
    const int aub  = lane >> 4;
    const int brow = (lane & 7) + (lane >> 4) * 8;
    const int bub  = (lane >> 3) & 1;

    float acc[4][4][4];
#pragma unroll
    for (int i = 0; i < 4; i++)
#pragma unroll
        for (int j = 0; j < 4; j++)
#pragma unroll
            for (int q = 0; q < 4; q++) acc[i][j][q] = 0.f;

    for (int c = 0; c < 16; c++) {
        int buf = c & 1;
        mwait(sb + buf * 8, (c >> 1) & 1);
        u32 Ab = SA + buf * 16384, Bb = SBB + buf * 16384;
#pragma unroll
        for (int s = 0; s < 4; s++) {
            u32 a4[4][4];
#pragma unroll
            for (int mt = 0; mt < 4; mt++) {
                int r = wr * 64 + mt * 16 + arow;
                u32 off = (u32)(r * 128 + (((s * 2 + aub) ^ (r & 7)) << 4));
                ldsm_x4(a4[mt], Ab + off);
            }
#pragma unroll
            for (int np = 0; np < 2; np++) {
                int n = wc * 32 + np * 16 + brow;
                u32 off = (u32)(n * 128 + (((s * 2 + bub) ^ (n & 7)) << 4));
                u32 b4[4];
                ldsm_x4(b4, Bb + off);
#pragma unroll
                for (int mt = 0; mt < 4; mt++) {
                    mma_fp16(acc[mt][np * 2 + 0], a4[mt], b4 + 0);
                    mma_fp16(acc[mt][np * 2 + 1], a4[mt], b4 + 2);
                }
            }
        }
        mbar_arrive(sb + 16 + buf * 8);
        if (tid == 0 && c < 14) issue(c + 2);
    }

    const int gate = bx >> 3;
    const float* __restrict__ bias =
        (gate == 0) ? b_i : (gate == 1) ? b_f : (gate == 2) ? b_g : b_o;
    const int bcol0 = (bx & 7) * 128 + wc * 32 + (lane & 3) * 2;
    float2 bv[4];
#pragma unroll
    for (int nt = 0; nt < 4; nt++)
        bv[nt] = make_float2(bias[bcol0 + nt * 8], bias[bcol0 + nt * 8 + 1]);

    const int colg = bx * 128 + wc * 32 + (lane & 3) * 2;
#pragma unroll
    for (int mt = 0; mt < 4; mt++) {
#pragma unroll
        for (int h2 = 0; h2 < 2; h2++) {
            int m = by * 128 + wr * 64 + mt * 16 + (lane >> 2) + h2 * 8;
            int bb = m >> 10, t = m & 1023;
            float* __restrict__ xp =
                ((t < 512) ? g_xp0 : g_xp1) + ((size_t)(t & 511) * 128 + bb) * 4096 + colg;
#pragma unroll
            for (int nt = 0; nt < 4; nt++) {
                float2 o = make_float2(acc[mt][nt][h2 * 2 + 0] + bv[nt].x,
                                       acc[mt][nt][h2 * 2 + 1] + bv[nt].y);
                *(float2*)(xp + nt * 8) = o;
            }
        }
    }
}

// ---- Phase 2 (persistent): 128 CTAs x 256 thr; fp16 h x fp16 Wh ------------
// Step boundary: CTAs 0..15 (producers of h chunks 0,1) bump g_early after
// their epilogue; every CTA's tid0 arrives at the main barrier, then polls
// g_early and issues chunks 0,1 of t+1 while waiting for the main barrier,
// overlapping the refill latency with the barrier tail.
__global__ void __launch_bounds__(256, 1) lstm_mma(float* __restrict__ out)
{
    extern __shared__ __align__(1024) char smem[];
    const u32 sb = sptr(smem);
    const int tid = threadIdx.x, lane = tid & 31, w = tid >> 5;
    const int cb = blockIdx.x;
    const u32 SBH = sb + 1024, SA = sb + 66560;   // Wh 64KB; 2 x 16KB A bufs

    if (tid == 0) {
        mbar_init(sb + 0, 1);   mbar_init(sb + 8, 1);     // full
        mbar_init(sb + 16, 256); mbar_init(sb + 24, 256); // empty
        mbar_init(sb + 32, 1);                            // Wh
        mbar_expect_tx(sb + 32, 65536);
        bulk_g2s(SBH, (const char*)g_whf + (size_t)cb * 65536, 65536, sb + 32);
    }
    __syncthreads();
    mwait(sb + 32, 0);

    const int arow = (lane & 7) + ((lane >> 3) & 1) * 8;
    const int aub  = lane >> 4;
    const int brow = (lane & 7) + (lane >> 4) * 8;
    const int bub  = (lane >> 3) & 1;
    const int r0 = w * 16 + (lane >> 2), p = lane & 3;
    const u32 aoff_base = (u32)((w * 16 + arow) * 128);
    const int ar7 = (w * 16 + arow) & 7;

    auto issue = [&](int t, int c) {
        int buf = c & 1;
        mwait(sb + 16 + buf * 8, ((c >> 1) & 1) ^ 1);
        mbar_expect_tx(sb + buf * 8, 16384);
        bulk_g2s(SA + buf * 16384,
                 (const char*)g_hf[t & 1] + (size_t)c * 16384, 16384, sb + buf * 8);
    };

    float cst[2][2] = {{0.f, 0.f}, {0.f, 0.f}};

    for (int t = 0; t < TT; t++) {
        if (t == 0 && tid == 0) { f_proxy(); issue(0, 0); issue(0, 1); }

        // prefetch xp gate values for this thread's 4 outputs (hide L2 latency)
        const float* xpb = ((t < 512) ? g_xp0 : g_xp1) + (size_t)(t & 511) * 524288;
        float2 xg[2][4];
#pragma unroll
        for (int half = 0; half < 2; half++) {
            const float* xr = xpb + (size_t)(r0 + half * 8) * 4096 + cb * 8 + p * 2;
            xg[half][0] = *(const float2*)(xr);
            xg[half][1] = *(const float2*)(xr + 1024);
            xg[half][2] = *(const float2*)(xr + 2048);
            xg[half][3] = *(const float2*)(xr + 3072);
        }

        float acc[4][4];
#pragma unroll
        for (int i = 0; i < 4; i++)
#pragma unroll
            for (int q = 0; q < 4; q++) acc[i][q] = 0.f;

        for (int c = 0; c < 16; c++) {
            int buf = c & 1;
            mwait(sb + buf * 8, (c >> 1) & 1);
            u32 Ab = SA + buf * 16384;
#pragma unroll
            for (int s = 0; s < 4; s++) {
                u32 ah[4];
                u32 aoff = aoff_base + (((s * 2 + aub) ^ ar7) << 4);
                ldsm_x4(ah, Ab + aoff);
                int kk2 = (c * 4 + s) * 2 + bub;
#pragma unroll
                for (int np = 0; np < 2; np++) {
                    int j = np * 16 + brow;
                    u32 boff = (u32)(j * 2048 + ((kk2 ^ (j & 7)) << 4));
                    u32 bh[4];
                    ldsm_x4(bh, SBH + boff);
                    mma_fp16(acc[np * 2 + 0], ah, bh + 0);
                    mma_fp16(acc[np * 2 + 1], ah, bh + 2);
                }
            }
            mbar_arrive(sb + 16 + buf * 8);
            if (tid == 0 && c < 14) issue(t, c + 2);
        }

        // epilogue: acc[0..3] = gates i,f,g,o at cols jj=2p,2p+1; rows r0, r0+8
        float hv[2][2];
#pragma unroll
        for (int half = 0; half < 2; half++) {
            int b = r0 + half * 8;
#pragma unroll
            for (int q = 0; q < 2; q++) {
                float iv = acc[0][half * 2 + q] + (q ? xg[half][0].y : xg[half][0].x);
                float fv = acc[1][half * 2 + q] + (q ? xg[half][1].y : xg[half][1].x);
                float gv = acc[2][half * 2 + q] + (q ? xg[half][2].y : xg[half][2].x);
                float ov = acc[3][half * 2 + q] + (q ? xg[half][3].y : xg[half][3].x);
                float si = 1.f / (1.f + expf(-iv));
                float sf = 1.f / (1.f + expf(-fv));
                float tg = tanhf(gv);
                float so = 1.f / (1.f + expf(-ov));
                cst[half][q] = sf * cst[half][q] + si * tg;
                hv[half][q] = so * tanhf(cst[half][q]);
            }
            __half f0 = __float2half_rn(hv[half][0]);
            __half f1 = __float2half_rn(hv[half][1]);
            u32 hw = (u32)(*(u16*)&f0) | ((u32)(*(u16*)&f1) << 16);
            u32 off = (u32)(cb >> 3) * 16384 + (u32)b * 128
                    + (u32)(((cb & 7) ^ (b & 7)) << 4) + (u32)p * 4;
            *(u32*)((char*)g_hf[(t + 1) & 1] + off) = hw;
        }

        if (t == TT - 1) {
#pragma unroll
            for (int half = 0; half < 2; half++) {
                int b = r0 + half * 8;
                float* o1 = out + (size_t)b * 1024 + cb * 8 + p * 2;
                o1[0] = hv[half][0]; o1[1] = hv[half][1];
                float* o2 = o1 + 131072;
                o2[0] = cst[half][0]; o2[1] = cst[half][1];
            }
        }

        if (t < TT - 1) {
            __syncthreads();
            if (tid == 0) {
                __threadfence();
                if (cb < 16) atomicAdd(&g_early, 1u);   // h chunks 0,1 published
                atomicAdd(&g_bar, 1u);
                // overlap refill of t+1 chunks 0,1 with the barrier tail
                unsigned etgt = 16u * (unsigned)(t + 1);
                while (ld_acq(&g_early) < etgt) __nanosleep(32);
                f_proxy();
                issue(t + 1, 0);
                issue(t + 1, 1);
                unsigned tgt = 128u * (unsigned)(t + 1);
                while (ld_acq(&g_bar) < tgt) __nanosleep(32);
            }
            __syncthreads();
        }
    }
}

// ---------------------------------------------------------------------------
extern "C" void kernel_launch(void* const* d_in, const int* in_sizes, int n_in,
                              void* d_out, int out_size)
{
    const float* x   = (const float*)d_in[0];
    const float* Wii = (const float*)d_in[1];
    const float* Wif = (const float*)d_in[2];
    const float* Wig = (const float*)d_in[3];
    const float* Wio = (const float*)d_in[4];
    const float* Whi = (const float*)d_in[5];
    const float* Whf = (const float*)d_in[6];
    const float* Whg = (const float*)d_in[7];
    const float* Who = (const float*)d_in[8];
    const float* b_i = (const float*)d_in[9];
    const float* b_f = (const float*)d_in[10];
    const float* b_g = (const float*)d_in[11];
    const float* b_o = (const float*)d_in[12];
    float* out = (float*)d_out;

    cudaFuncSetAttribute(xproj_mma, cudaFuncAttributeMaxDynamicSharedMemorySize, 66560);
    cudaFuncSetAttribute(lstm_mma,  cudaFuncAttributeMaxDynamicSharedMemorySize, 99328);

    init_kernel<<<256, 256>>>();
    conv_x_kernel<<<65536, 256>>>(x);
    conv_wi_kernel<<<2048, 256>>>(Wii, Wif, Wig, Wio);
    conv_wh_kernel<<<2048, 256>>>(Whi, Whf, Whg, Who);

    dim3 g1(32, 1024);
    xproj_mma<<<g1, 256, 66560>>>(b_i, b_f, b_g, b_o);
    lstm_mma<<<128, 256, 99328>>>(out);
}

// round 17
// speedup vs baseline: 1.9297x; 1.0665x over previous
#include <cuda_runtime.h>
#include <cuda_bf16.h>
#include <cuda_fp16.h>

typedef unsigned int u32;
typedef unsigned long long u64;
typedef unsigned short u16;

#define TT 1024

// ---- device scratch --------------------------------------------------------
__device__ __align__(1024) float g_xp0[(size_t)512 * 128 * 4096];
__device__ __align__(1024) float g_xp1[(size_t)512 * 128 * 4096];
__device__ __align__(1024) __half g_xf[(size_t)128 * 1024 * 1024];   // x fp16 A-image
__device__ __align__(1024) __half g_wif[(size_t)4096 * 1024];        // Wi fp16 B-image
__device__ __align__(1024) __half g_whf[(size_t)4096 * 1024];        // Wh fp16 B-image
// h image ping-pong: 16 chunks x [128 b x 64 k] fp16, 128B rows, unit u^(b&7)
__device__ __align__(1024) __half g_hf[2][16 * 128 * 64];
__device__ unsigned g_bar;

// ---- PTX helpers (base sm_103 safe) ---------------------------------------
__device__ __forceinline__ u32 sptr(const void* p) {
    u32 a;
    asm("{ .reg .u64 t; cvta.to.shared.u64 t, %1; cvt.u32.u64 %0, t; }" : "=r"(a) : "l"(p));
    return a;
}
__device__ __forceinline__ void mbar_init(u32 m, u32 cnt) {
    asm volatile("mbarrier.init.shared.b64 [%0], %1;" :: "r"(m), "r"(cnt) : "memory");
}
__device__ __forceinline__ void mbar_expect_tx(u32 m, u32 bytes) {
    asm volatile("mbarrier.arrive.expect_tx.shared.b64 _, [%0], %1;" :: "r"(m), "r"(bytes) : "memory");
}
__device__ __forceinline__ void mbar_arrive(u32 m) {
    asm volatile("mbarrier.arrive.shared.b64 _, [%0];" :: "r"(m) : "memory");
}
__device__ __forceinline__ void mwait(u32 m, u32 parity) {
    asm volatile(
        "{\n\t.reg .pred P;\n"
        "W%=:\n\tmbarrier.try_wait.parity.acquire.cta.shared::cta.b64 P, [%0], %1, 0x989680;\n"
        "\t@P bra D%=;\n\tbra W%=;\nD%=:\n\t}" :: "r"(m), "r"(parity) : "memory");
}
__device__ __forceinline__ void bulk_g2s(u32 dst, const void* src, u32 bytes, u32 m) {
    asm volatile(
        "cp.async.bulk.shared::cluster.global.mbarrier::complete_tx::bytes [%0], [%1], %2, [%3];"
        :: "r"(dst), "l"((u64)__cvta_generic_to_global(src)), "r"(bytes), "r"(m) : "memory");
}
__device__ __forceinline__ void f_proxy() { asm volatile("fence.proxy.async;" ::: "memory"); }
__device__ __forceinline__ unsigned ld_acq(const unsigned* p) {
    unsigned v;
    asm volatile("ld.global.acquire.gpu.u32 %0, [%1];" : "=r"(v) : "l"(p));
    return v;
}
__device__ __forceinline__ void ldsm_x4(u32 (&r)[4], u32 addr) {
    asm volatile("ldmatrix.sync.aligned.m8n8.x4.shared.b16 {%0,%1,%2,%3}, [%4];"
                 : "=r"(r[0]), "=r"(r[1]), "=r"(r[2]), "=r"(r[3]) : "r"(addr));
}
__device__ __forceinline__ void mma_fp16(float (&d)[4], const u32 (&a)[4], const u32* b) {
    asm volatile(
        "mma.sync.aligned.m16n8k16.row.col.f32.f16.f16.f32 "
        "{%0,%1,%2,%3}, {%4,%5,%6,%7}, {%8,%9}, {%0,%1,%2,%3};"
        : "+f"(d[0]), "+f"(d[1]), "+f"(d[2]), "+f"(d[3])
        : "r"(a[0]), "r"(a[1]), "r"(a[2]), "r"(a[3]), "r"(b[0]), "r"(b[1]));
}

// ---- init ------------------------------------------------------------------
__global__ void init_kernel() {
    int i = blockIdx.x * blockDim.x + threadIdx.x;   // 65536
    ((u32*)g_hf[0])[i] = 0u;
    if (i == 0) g_bar = 0u;
}

// ---- conversions to blocked swizzled images --------------------------------
// x A-image: [mt][kc(16)][128 rows x 64 k] fp16, row=128B, unit u -> u^(row&7)
__global__ void conv_x_kernel(const float* __restrict__ x) {
    size_t idx = (size_t)blockIdx.x * 256 + threadIdx.x;   // 16,777,216
    u32 m = (u32)(idx >> 7), ku = (u32)(idx & 127);
    const float4* src = (const float4*)(x + (size_t)m * 1024 + ku * 8);
    float4 a = src[0], b = src[1];
    float v[8] = {a.x, a.y, a.z, a.w, b.x, b.y, b.z, b.w};
    union { u16 s[8]; uint4 q; } F;
#pragma unroll
    for (int i = 0; i < 8; i++) {
        __half hv = __float2half_rn(v[i]);
        F.s[i] = *(u16*)&hv;
    }
    u32 mt = m >> 7, r = m & 127, kc = ku >> 3, uu = ku & 7;
    size_t off = ((size_t)(mt * 16 + kc) << 13) + (r << 6) + ((uu ^ (r & 7)) << 3);
    *(uint4*)(g_xf + off) = F.q;
}
// Wi B-image: [nt(32)][kc(16)][128 n x 64 k] fp16
__global__ void conv_wi_kernel(const float* __restrict__ W0, const float* __restrict__ W1,
                               const float* __restrict__ W2, const float* __restrict__ W3) {
    u32 idx = blockIdx.x * 256 + threadIdx.x;   // 524288
    u32 n = idx & 4095, ku = idx >> 12;
    const float* __restrict__ W = (n < 1024) ? W0 : (n < 2048) ? W1 : (n < 3072) ? W2 : W3;
    u32 col = n & 1023;
    union { u16 s[8]; uint4 q; } F;
#pragma unroll
    for (int i = 0; i < 8; i++) {
        __half hv = __float2half_rn(W[(size_t)(ku * 8 + i) * 1024 + col]);
        F.s[i] = *(u16*)&hv;
    }
    u32 nt = n >> 7, r = n & 127, kc = ku >> 3, uu = ku & 7;
    size_t off = ((size_t)(nt * 16 + kc) << 13) + (r << 6) + ((uu ^ (r & 7)) << 3);
    *(uint4*)(g_wif + off) = F.q;
}
// Wh B-image: [cb(128)][32 rows(j=g*8+(n&7)) x 1024 k] fp16 single, row=2048B
__global__ void conv_wh_kernel(const float* __restrict__ W0, const float* __restrict__ W1,
                               const float* __restrict__ W2, const float* __restrict__ W3) {
    u32 idx = blockIdx.x * 256 + threadIdx.x;   // 524288
    u32 n = idx & 1023, ku = (idx >> 10) & 127, g = idx >> 17;
    const float* __restrict__ W = (g == 0) ? W0 : (g == 1) ? W1 : (g == 2) ? W2 : W3;
    union { u16 s[8]; uint4 q; } F;
#pragma unroll
    for (int i = 0; i < 8; i++) {
        __half hv = __float2half_rn(W[(size_t)(ku * 8 + i) * 1024 + n]);
        F.s[i] = *(u16*)&hv;
    }
    u32 cb = n >> 3, j = g * 8 + (n & 7);
    size_t off = ((size_t)cb << 15) + (j << 10) + ((ku ^ (j & 7)) << 3);
    *(uint4*)(g_whf + off) = F.q;
}

// ---- Phase 1: x_proj = x @ Wi + bias. fp16 MMA (unchanged) -----------------
__global__ void __launch_bounds__(256, 1) xproj_mma(
    const float* __restrict__ b_i, const float* __restrict__ b_f,
    const float* __restrict__ b_g, const float* __restrict__ b_o)
{
    extern __shared__ __align__(1024) char smem[];
    const u32 sb = sptr(smem);
    const int tid = threadIdx.x, lane = tid & 31, w = tid >> 5;
    const int bx = blockIdx.x, by = blockIdx.y;
    const u32 SA = sb + 1024, SBB = sb + 33792;

    if (tid == 0) {
        mbar_init(sb + 0, 1);   mbar_init(sb + 8, 1);     // full
        mbar_init(sb + 16, 256); mbar_init(sb + 24, 256); // empty
    }
    __syncthreads();

    const char* ax = (const char*)g_xf + (size_t)by * 262144;
    const char* bw = (const char*)g_wif + (size_t)bx * 262144;

    auto issue = [&](int c) {
        int buf = c & 1;
        mwait(sb + 16 + buf * 8, ((c >> 1) & 1) ^ 1);
        mbar_expect_tx(sb + buf * 8, 32768);
        bulk_g2s(SA + buf * 16384,  ax + (size_t)c * 16384, 16384, sb + buf * 8);
        bulk_g2s(SBB + buf * 16384, bw + (size_t)c * 16384, 16384, sb + buf * 8);
    };
    if (tid == 0) { issue(0); issue(1); }

    const int wr = w >> 2, wc = w & 3;
    const int arow = (lane & 7) + ((lane >> 3) & 1) * 8;
    const int aub  = lane >> 4;
    const int brow = (lane & 7) + (lane >> 4) * 8;
    const int bub  = (lane >> 3) & 1;

    float acc[4][4][4];
#pragma unroll
    for (int i = 0; i < 4; i++)
#pragma unroll
        for (int j = 0; j < 4; j++)
#pragma unroll
            for (int q = 0; q < 4; q++) acc[i][j][q] = 0.f;

    for (int c = 0; c < 16; c++) {
        int buf = c & 1;
        mwait(sb + buf * 8, (c >> 1) & 1);
        u32 Ab = SA + buf * 16384, Bb = SBB + buf * 16384;
#pragma unroll
        for (int s = 0; s < 4; s++) {
            u32 a4[4][4];
#pragma unroll
            for (int mt = 0; mt < 4; mt++) {
                int r = wr * 64 + mt * 16 + arow;
                u32 off = (u32)(r * 128 + (((s * 2 + aub) ^ (r & 7)) << 4));
                ldsm_x4(a4[mt], Ab + off);
            }
#pragma unroll
            for (int np = 0; np < 2; np++) {
                int n = wc * 32 + np * 16 + brow;
                u32 off = (u32)(n * 128 + (((s * 2 + bub) ^ (n & 7)) << 4));
                u32 b4[4];
                ldsm_x4(b4, Bb + off);
#pragma unroll
                for (int mt = 0; mt < 4; mt++) {
                    mma_fp16(acc[mt][np * 2 + 0], a4[mt], b4 + 0);
                    mma_fp16(acc[mt][np * 2 + 1], a4[mt], b4 + 2);
                }
            }
        }
        mbar_arrive(sb + 16 + buf * 8);
        if (tid == 0 && c < 14) issue(c + 2);
    }

    const int gate = bx >> 3;
    const float* __restrict__ bias =
        (gate == 0) ? b_i : (gate == 1) ? b_f : (gate == 2) ? b_g : b_o;
    const int bcol0 = (bx & 7) * 128 + wc * 32 + (lane & 3) * 2;
    float2 bv[4];
#pragma unroll
    for (int nt = 0; nt < 4; nt++)
        bv[nt] = make_float2(bias[bcol0 + nt * 8], bias[bcol0 + nt * 8 + 1]);

    const int colg = bx * 128 + wc * 32 + (lane & 3) * 2;
#pragma unroll
    for (int mt = 0; mt < 4; mt++) {
#pragma unroll
        for (int h2 = 0; h2 < 2; h2++) {
            int m = by * 128 + wr * 64 + mt * 16 + (lane >> 2) + h2 * 8;
            int bb = m >> 10, t = m & 1023;
            float* __restrict__ xp =
                ((t < 512) ? g_xp0 : g_xp1) + ((size_t)(t & 511) * 128 + bb) * 4096 + colg;
#pragma unroll
            for (int nt = 0; nt < 4; nt++) {
                float2 o = make_float2(acc[mt][nt][h2 * 2 + 0] + bv[nt].x,
                                       acc[mt][nt][h2 * 2 + 1] + bv[nt].y);
                *(float2*)(xp + nt * 8) = o;
            }
        }
    }
}

// ---- Phase 2 (persistent): 128 CTAs x 256 thr; fp16 h x fp16 Wh ------------
// Chunk order STAGGERED per CTA: CTA cb processes chunks (cb>>3 + c) & 15,
// spreading the 128 CTAs across all 16 chunks at any instant -> flattens the
// L2 request queue (all CTAs read the same 256KB h image every step) and
// reduces per-step completion skew at the global barrier.
__global__ void __launch_bounds__(256, 1) lstm_mma(float* __restrict__ out)
{
    extern __shared__ __align__(1024) char smem[];
    const u32 sb = sptr(smem);
    const int tid = threadIdx.x, lane = tid & 31, w = tid >> 5;
    const int cb = blockIdx.x;
    const int cbase = cb >> 3;                    // stagger start chunk (0..15)
    const u32 SBH = sb + 1024, SA = sb + 66560;   // Wh 64KB; 2 x 16KB A bufs

    if (tid == 0) {
        mbar_init(sb + 0, 1);   mbar_init(sb + 8, 1);     // full
        mbar_init(sb + 16, 256); mbar_init(sb + 24, 256); // empty
        mbar_init(sb + 32, 1);                            // Wh
        mbar_expect_tx(sb + 32, 65536);
        bulk_g2s(SBH, (const char*)g_whf + (size_t)cb * 65536, 65536, sb + 32);
    }
    __syncthreads();
    mwait(sb + 32, 0);

    const int arow = (lane & 7) + ((lane >> 3) & 1) * 8;
    const int aub  = lane >> 4;
    const int brow = (lane & 7) + (lane >> 4) * 8;
    const int bub  = (lane >> 3) & 1;
    const int r0 = w * 16 + (lane >> 2), p = lane & 3;
    const u32 aoff_base = (u32)((w * 16 + arow) * 128);
    const int ar7 = (w * 16 + arow) & 7;

    // c = sequence position (buffer/parity); actual chunk = (cbase + c) & 15
    auto issue = [&](int t, int c) {
        int buf = c & 1;
        int ch = (cbase + c) & 15;
        mwait(sb + 16 + buf * 8, ((c >> 1) & 1) ^ 1);
        mbar_expect_tx(sb + buf * 8, 16384);
        bulk_g2s(SA + buf * 16384,
                 (const char*)g_hf[t & 1] + (size_t)ch * 16384, 16384, sb + buf * 8);
    };

    float cst[2][2] = {{0.f, 0.f}, {0.f, 0.f}};

    for (int t = 0; t < TT; t++) {
        if (tid == 0) { f_proxy(); issue(t, 0); issue(t, 1); }

        // prefetch xp gate values for this thread's 4 outputs (hide L2 latency)
        const float* xpb = ((t < 512) ? g_xp0 : g_xp1) + (size_t)(t & 511) * 524288;
        float2 xg[2][4];
#pragma unroll
        for (int half = 0; half < 2; half++) {
            const float* xr = xpb + (size_t)(r0 + half * 8) * 4096 + cb * 8 + p * 2;
            xg[half][0] = *(const float2*)(xr);
            xg[half][1] = *(const float2*)(xr + 1024);
            xg[half][2] = *(const float2*)(xr + 2048);
            xg[half][3] = *(const float2*)(xr + 3072);
        }

        float acc[4][4];
#pragma unroll
        for (int i = 0; i < 4; i++)
#pragma unroll
            for (int q = 0; q < 4; q++) acc[i][q] = 0.f;

        for (int c = 0; c < 16; c++) {
            int buf = c & 1;
            int ch = (cbase + c) & 15;
            mwait(sb + buf * 8, (c >> 1) & 1);
            u32 Ab = SA + buf * 16384;
#pragma unroll
            for (int s = 0; s < 4; s++) {
                u32 ah[4];
                u32 aoff = aoff_base + (((s * 2 + aub) ^ ar7) << 4);
                ldsm_x4(ah, Ab + aoff);
                int kk2 = (ch * 4 + s) * 2 + bub;
#pragma unroll
                for (int np = 0; np < 2; np++) {
                    int j = np * 16 + brow;
                    u32 boff = (u32)(j * 2048 + ((kk2 ^ (j & 7)) << 4));
                    u32 bh[4];
                    ldsm_x4(bh, SBH + boff);
                    mma_fp16(acc[np * 2 + 0], ah, bh + 0);
                    mma_fp16(acc[np * 2 + 1], ah, bh + 2);
                }
            }
            mbar_arrive(sb + 16 + buf * 8);
            if (tid == 0 && c < 14) issue(t, c + 2);
        }

        // epilogue: acc[0..3] = gates i,f,g,o at cols jj=2p,2p+1; rows r0, r0+8
        float hv[2][2];
#pragma unroll
        for (int half = 0; half < 2; half++) {
            int b = r0 + half * 8;
#pragma unroll
            for (int q = 0; q < 2; q++) {
                float iv = acc[0][half * 2 + q] + (q ? xg[half][0].y : xg[half][0].x);
                float fv = acc[1][half * 2 + q] + (q ? xg[half][1].y : xg[half][1].x);
                float gv = acc[2][half * 2 + q] + (q ? xg[half][2].y : xg[half][2].x);
                float ov = acc[3][half * 2 + q] + (q ? xg[half][3].y : xg[half][3].x);
                float si = 1.f / (1.f + expf(-iv));
                float sf = 1.f / (1.f + expf(-fv));
                float tg = tanhf(gv);
                float so = 1.f / (1.f + expf(-ov));
                cst[half][q] = sf * cst[half][q] + si * tg;
                hv[half][q] = so * tanhf(cst[half][q]);
            }
            __half f0 = __float2half_rn(hv[half][0]);
            __half f1 = __float2half_rn(hv[half][1]);
            u32 hw = (u32)(*(u16*)&f0) | ((u32)(*(u16*)&f1) << 16);
            u32 off = (u32)(cb >> 3) * 16384 + (u32)b * 128
                    + (u32)(((cb & 7) ^ (b & 7)) << 4) + (u32)p * 4;
            *(u32*)((char*)g_hf[(t + 1) & 1] + off) = hw;
        }

        if (t == TT - 1) {
#pragma unroll
            for (int half = 0; half < 2; half++) {
                int b = r0 + half * 8;
                float* o1 = out + (size_t)b * 1024 + cb * 8 + p * 2;
                o1[0] = hv[half][0]; o1[1] = hv[half][1];
                float* o2 = o1 + 131072;
                o2[0] = cst[half][0]; o2[1] = cst[half][1];
            }
        }

        if (t < TT - 1) {   // global barrier (R8-proven)
            __syncthreads();
            if (tid == 0) {
                __threadfence();
                atomicAdd(&g_bar, 1u);
                unsigned tgt = 128u * (unsigned)(t + 1);
                while (ld_acq(&g_bar) < tgt) __nanosleep(64);
            }
            __syncthreads();
        }
    }
}

// ---------------------------------------------------------------------------
extern "C" void kernel_launch(void* const* d_in, const int* in_sizes, int n_in,
                              void* d_out, int out_size)
{
    const float* x   = (const float*)d_in[0];
    const float* Wii = (const float*)d_in[1];
    const float* Wif = (const float*)d_in[2];
    const float* Wig = (const float*)d_in[3];
    const float* Wio = (const float*)d_in[4];
    const float* Whi = (const float*)d_in[5];
    const float* Whf = (const float*)d_in[6];
    const float* Whg = (const float*)d_in[7];
    const float* Who = (const float*)d_in[8];
    const float* b_i = (const float*)d_in[9];
    const float* b_f = (const float*)d_in[10];
    const float* b_g = (const float*)d_in[11];
    const float* b_o = (const float*)d_in[12];
    float* out = (float*)d_out;

    cudaFuncSetAttribute(xproj_mma, cudaFuncAttributeMaxDynamicSharedMemorySize, 66560);
    cudaFuncSetAttribute(lstm_mma,  cudaFuncAttributeMaxDynamicSharedMemorySize, 99328);

    init_kernel<<<256, 256>>>();
    conv_x_kernel<<<65536, 256>>>(x);
    conv_wi_kernel<<<2048, 256>>>(Wii, Wif, Wig, Wio);
    conv_wh_kernel<<<2048, 256>>>(Whi, Whf, Whg, Who);

    dim3 g1(32, 1024);
    xproj_mma<<<g1, 256, 66560>>>(b_i, b_f, b_g, b_o);
    lstm_mma<<<128, 256, 99328>>>(out);
}